// round 1
// baseline (speedup 1.0000x reference)
#include <cuda_runtime.h>
#include <math.h>

// Problem dims (fixed by the reference)
#define SS   2048          // sequence
#define DM   2048          // model dim
#define NH   16            // q heads
#define NKV  4             // kv heads
#define HD   128           // head dim
#define NE   8             // experts
#define FF   4096          // ffn dim
#define QKVN 3072          // (NH + 2*NKV) * HD
#define MAXROWS 5120       // padded MoE rows (4096 + 8*128 slack)
#define MAXTILES 40        // MAXROWS / 128

// ---------------- scratch (static device allocations) ----------------
__device__ float g_xln[SS*DM];                   // LN output (reused for LN1 and LN2)
__device__ float g_qkv[SS*QKVN];
__device__ float g_Q[NH*SS*HD];
__device__ float g_K[NKV*SS*HD];
__device__ float g_V[NKV*SS*HD];
__device__ float g_P[67108864];                  // 16*2048*2048 scores/probs (256MB)
__device__ float g_oc[SS*DM];                    // attention output, head-concat layout
__device__ float g_res2[SS*DM];                  // residual2
__device__ float g_gbuf[MAXROWS*FF];             // MoE gate acts -> then h = silu(g)*u
__device__ float g_dout[MAXROWS*DM];             // MoE down outputs (pre-weighted)
__device__ float g_topw[SS*2];
__device__ int   g_topid[SS*2];
__device__ int   g_cnt[NE];
__device__ int   g_cnt2[NE];
__device__ int   g_off[NE];
__device__ int   g_rows[MAXROWS];
__device__ float g_wv[MAXROWS];
__device__ int   g_slot[SS*2];
__device__ int   g_tileexp[MAXTILES];

// ---------------- SGEMM tile core ----------------
// C tile 128x128, BK=8, 256 threads, 8x8 per-thread.
// A: row-major [.,lda], optional row gather via rowmap.
// BT=false: B is [K,N] row-major (ldb=N).  BT=true: B is [N,K] row-major (ldb=K).
template<bool BT>
__device__ __forceinline__ void sgemm_tile(
    float (&acc)[8][8],
    const float* __restrict__ A, int lda, const int* __restrict__ rowmap, int m0,
    const float* __restrict__ B, int ldb, int n0,
    int kbeg, int kend, float* __restrict__ As, float* __restrict__ Bs)
{
  const int tid  = threadIdx.x;
  const int arow = tid >> 1;
  const int acol = (tid & 1) << 2;
  const int r    = rowmap ? rowmap[m0 + arow] : (m0 + arow);
  const float* Ap = A + (size_t)r * lda + acol;
  const float* Bp;
  int brow, bcol;
  if (BT) { brow = tid >> 1; bcol = (tid & 1) << 2;  Bp = B + (size_t)(n0 + brow) * ldb + bcol; }
  else    { brow = tid >> 5; bcol = (tid & 31) << 2; Bp = B + (size_t)brow * ldb + n0 + bcol; }
  const int tx = tid & 15, ty = tid >> 4;

  for (int k0 = kbeg; k0 < kend; k0 += 8) {
    float4 av = *(const float4*)(Ap + k0);
    As[(acol+0)*128 + arow] = av.x;
    As[(acol+1)*128 + arow] = av.y;
    As[(acol+2)*128 + arow] = av.z;
    As[(acol+3)*128 + arow] = av.w;
    if (BT) {
      float4 bv = *(const float4*)(Bp + k0);
      Bs[(bcol+0)*128 + brow] = bv.x;
      Bs[(bcol+1)*128 + brow] = bv.y;
      Bs[(bcol+2)*128 + brow] = bv.z;
      Bs[(bcol+3)*128 + brow] = bv.w;
    } else {
      float4 bv = *(const float4*)(Bp + (size_t)k0 * ldb);
      *(float4*)(Bs + brow*128 + bcol) = bv;
    }
    __syncthreads();
#pragma unroll
    for (int kk = 0; kk < 8; kk++) {
      float ar[8], br[8];
      *(float4*)(&ar[0]) = *(const float4*)(As + kk*128 + ty*8);
      *(float4*)(&ar[4]) = *(const float4*)(As + kk*128 + ty*8 + 4);
      *(float4*)(&br[0]) = *(const float4*)(Bs + kk*128 + tx*8);
      *(float4*)(&br[4]) = *(const float4*)(Bs + kk*128 + tx*8 + 4);
#pragma unroll
      for (int i = 0; i < 8; i++)
#pragma unroll
        for (int j = 0; j < 8; j++)
          acc[i][j] = fmaf(ar[i], br[j], acc[i][j]);
    }
    __syncthreads();
  }
}

// ---------------- LayerNorm ----------------
__global__ __launch_bounds__(256) void k_ln(const float* __restrict__ X,
    const float* __restrict__ w, const float* __restrict__ b, float* __restrict__ Y)
{
  const int row = blockIdx.x;
  const float* x = X + (size_t)row * DM;
  float s = 0.f, ss = 0.f;
  for (int d = threadIdx.x*4; d < DM; d += 1024) {
    float4 v = *(const float4*)(x + d);
    s  += v.x + v.y + v.z + v.w;
    ss += v.x*v.x + v.y*v.y + v.z*v.z + v.w*v.w;
  }
  __shared__ float shA[8], shB[8];
  const int lane = threadIdx.x & 31, wi = threadIdx.x >> 5;
  for (int o = 16; o; o >>= 1) { s += __shfl_xor_sync(0xffffffffu, s, o); ss += __shfl_xor_sync(0xffffffffu, ss, o); }
  if (lane == 0) { shA[wi] = s; shB[wi] = ss; }
  __syncthreads();
  float st = 0.f, sst = 0.f;
#pragma unroll
  for (int k = 0; k < 8; k++) { st += shA[k]; sst += shB[k]; }
  const float mean = st / (float)DM;
  const float var  = sst / (float)DM - mean*mean;
  const float rstd = rsqrtf(var + 1e-5f);
  for (int d = threadIdx.x*4; d < DM; d += 1024) {
    float4 v = *(const float4*)(x + d);
    float4 wv = *(const float4*)(w + d);
    float4 bv = *(const float4*)(b + d);
    float4 o;
    o.x = (v.x-mean)*rstd*wv.x + bv.x;
    o.y = (v.y-mean)*rstd*wv.y + bv.y;
    o.z = (v.z-mean)*rstd*wv.z + bv.z;
    o.w = (v.w-mean)*rstd*wv.w + bv.w;
    *(float4*)(Y + (size_t)row*DM + d) = o;
  }
}

__global__ __launch_bounds__(256) void k_ln2(const float* __restrict__ w, const float* __restrict__ b)
{
  // wrapper: LN over g_res2 -> g_xln (so no host-side symbol addresses needed)
  const int row = blockIdx.x;
  const float* x = g_res2 + (size_t)row * DM;
  float s = 0.f, ss = 0.f;
  for (int d = threadIdx.x*4; d < DM; d += 1024) {
    float4 v = *(const float4*)(x + d);
    s  += v.x + v.y + v.z + v.w;
    ss += v.x*v.x + v.y*v.y + v.z*v.z + v.w*v.w;
  }
  __shared__ float shA[8], shB[8];
  const int lane = threadIdx.x & 31, wi = threadIdx.x >> 5;
  for (int o = 16; o; o >>= 1) { s += __shfl_xor_sync(0xffffffffu, s, o); ss += __shfl_xor_sync(0xffffffffu, ss, o); }
  if (lane == 0) { shA[wi] = s; shB[wi] = ss; }
  __syncthreads();
  float st = 0.f, sst = 0.f;
#pragma unroll
  for (int k = 0; k < 8; k++) { st += shA[k]; sst += shB[k]; }
  const float mean = st / (float)DM;
  const float var  = sst / (float)DM - mean*mean;
  const float rstd = rsqrtf(var + 1e-5f);
  for (int d = threadIdx.x*4; d < DM; d += 1024) {
    float4 v = *(const float4*)(x + d);
    float4 wv = *(const float4*)(w + d);
    float4 bv = *(const float4*)(b + d);
    float4 o;
    o.x = (v.x-mean)*rstd*wv.x + bv.x;
    o.y = (v.y-mean)*rstd*wv.y + bv.y;
    o.z = (v.z-mean)*rstd*wv.z + bv.z;
    o.w = (v.w-mean)*rstd*wv.w + bv.w;
    *(float4*)(g_xln + (size_t)row*DM + d) = o;
  }
}

__global__ __launch_bounds__(256) void k_ln1(const float* __restrict__ hidden,
    const float* __restrict__ w, const float* __restrict__ b)
{
  // forwards to generic by inlining would duplicate; just call pattern: hidden -> g_xln
  const int row = blockIdx.x;
  const float* x = hidden + (size_t)row * DM;
  float s = 0.f, ss = 0.f;
  for (int d = threadIdx.x*4; d < DM; d += 1024) {
    float4 v = *(const float4*)(x + d);
    s  += v.x + v.y + v.z + v.w;
    ss += v.x*v.x + v.y*v.y + v.z*v.z + v.w*v.w;
  }
  __shared__ float shA[8], shB[8];
  const int lane = threadIdx.x & 31, wi = threadIdx.x >> 5;
  for (int o = 16; o; o >>= 1) { s += __shfl_xor_sync(0xffffffffu, s, o); ss += __shfl_xor_sync(0xffffffffu, ss, o); }
  if (lane == 0) { shA[wi] = s; shB[wi] = ss; }
  __syncthreads();
  float st = 0.f, sst = 0.f;
#pragma unroll
  for (int k = 0; k < 8; k++) { st += shA[k]; sst += shB[k]; }
  const float mean = st / (float)DM;
  const float var  = sst / (float)DM - mean*mean;
  const float rstd = rsqrtf(var + 1e-5f);
  for (int d = threadIdx.x*4; d < DM; d += 1024) {
    float4 v = *(const float4*)(x + d);
    float4 wv = *(const float4*)(w + d);
    float4 bv = *(const float4*)(b + d);
    float4 o;
    o.x = (v.x-mean)*rstd*wv.x + bv.x;
    o.y = (v.y-mean)*rstd*wv.y + bv.y;
    o.z = (v.z-mean)*rstd*wv.z + bv.z;
    o.w = (v.w-mean)*rstd*wv.w + bv.w;
    *(float4*)(g_xln + (size_t)row*DM + d) = o;
  }
}

// ---------------- QKV GEMM: g_qkv = g_xln @ wqkv + bqkv ----------------
__global__ __launch_bounds__(256) void k_gemm_qkv(const float* __restrict__ W,
                                                  const float* __restrict__ bias)
{
  __shared__ __align__(16) float As[8*128];
  __shared__ __align__(16) float Bs[8*128];
  float acc[8][8] = {};
  const int m0 = blockIdx.y * 128, n0 = blockIdx.x * 128;
  sgemm_tile<false>(acc, g_xln, DM, nullptr, m0, W, QKVN, n0, 0, DM, As, Bs);
  const int tx = threadIdx.x & 15, ty = threadIdx.x >> 4;
  const int row0 = m0 + ty*8, col0 = n0 + tx*8;
#pragma unroll
  for (int i = 0; i < 8; i++) {
    float* cp = g_qkv + (size_t)(row0+i)*QKVN + col0;
    float4 a, b;
    a.x = acc[i][0]+bias[col0+0]; a.y = acc[i][1]+bias[col0+1];
    a.z = acc[i][2]+bias[col0+2]; a.w = acc[i][3]+bias[col0+3];
    b.x = acc[i][4]+bias[col0+4]; b.y = acc[i][5]+bias[col0+5];
    b.z = acc[i][6]+bias[col0+6]; b.w = acc[i][7]+bias[col0+7];
    *(float4*)cp = a; *(float4*)(cp+4) = b;
  }
}

// ---------------- RoPE + QKV split ----------------
__global__ __launch_bounds__(256) void k_rope(const float* __restrict__ cosb,
                                              const float* __restrict__ sinb)
{
  const int s = blockIdx.y;
  const int col = blockIdx.x * 256 + threadIdx.x;
  const float* qrow = g_qkv + (size_t)s * QKVN;
  const float x = qrow[col];
  if (col < NH*HD) {
    const int h = col >> 7, d = col & 127;
    const float c = cosb[s*HD+d], sn = sinb[s*HD+d];
    const float p = (d < 64) ? -qrow[col+64] : qrow[col-64];
    g_Q[((size_t)h*SS + s)*HD + d] = x*c + p*sn;
  } else if (col < (NH+NKV)*HD) {
    const int cc = col - NH*HD;
    const int h = cc >> 7, d = cc & 127;
    const float c = cosb[s*HD+d], sn = sinb[s*HD+d];
    const float p = (d < 64) ? -qrow[col+64] : qrow[col-64];
    g_K[((size_t)h*SS + s)*HD + d] = x*c + p*sn;
  } else {
    const int cc = col - (NH+NKV)*HD;
    const int h = cc >> 7, d = cc & 127;
    g_V[((size_t)h*SS + s)*HD + d] = x;
  }
}

// ---------------- scores = scale * Q @ K^T (causal tile skip) ----------------
__global__ __launch_bounds__(256) void k_scores(float scale)
{
  if (blockIdx.x > blockIdx.y) return;       // strictly-upper tile: never read
  const int h = blockIdx.z;
  __shared__ __align__(16) float As[8*128];
  __shared__ __align__(16) float Bs[8*128];
  float acc[8][8] = {};
  const int m0 = blockIdx.y * 128, n0 = blockIdx.x * 128;
  sgemm_tile<true>(acc, g_Q + (size_t)h*SS*HD, HD, nullptr, m0,
                   g_K + (size_t)(h>>2)*SS*HD, HD, n0, 0, HD, As, Bs);
  const int tx = threadIdx.x & 15, ty = threadIdx.x >> 4;
  const int row0 = m0 + ty*8, col0 = n0 + tx*8;
  float* Ph = g_P + (size_t)h*SS*SS;
#pragma unroll
  for (int i = 0; i < 8; i++) {
    float* cp = Ph + (size_t)(row0+i)*SS + col0;
    float4 a, b;
    a.x = acc[i][0]*scale; a.y = acc[i][1]*scale; a.z = acc[i][2]*scale; a.w = acc[i][3]*scale;
    b.x = acc[i][4]*scale; b.y = acc[i][5]*scale; b.z = acc[i][6]*scale; b.w = acc[i][7]*scale;
    *(float4*)cp = a; *(float4*)(cp+4) = b;
  }
}

// ---------------- causal softmax in place (zero-pads row to 128 boundary) ----------------
__global__ __launch_bounds__(256) void k_softmax()
{
  const int i = blockIdx.x, h = blockIdx.y;
  float* row = g_P + ((size_t)h*SS + i)*SS;
  const int jm = i;                        // inclusive last valid col
  const int jend = ((i >> 7) + 1) << 7;    // zero-pad to tile boundary
  __shared__ float buf[2048];
  __shared__ float redA[8], redB[8];
  const int tid = threadIdx.x;
  float mx = -1e30f;
  for (int j = tid; j <= jm; j += 256) { float v = row[j]; buf[j] = v; mx = fmaxf(mx, v); }
  for (int o = 16; o; o >>= 1) mx = fmaxf(mx, __shfl_xor_sync(0xffffffffu, mx, o));
  if ((tid & 31) == 0) redA[tid >> 5] = mx;
  __syncthreads();
  float m = redA[0];
#pragma unroll
  for (int k = 1; k < 8; k++) m = fmaxf(m, redA[k]);
  float s = 0.f;
  for (int j = tid; j <= jm; j += 256) { float e = expf(buf[j] - m); buf[j] = e; s += e; }
  for (int o = 16; o; o >>= 1) s += __shfl_xor_sync(0xffffffffu, s, o);
  if ((tid & 31) == 0) redB[tid >> 5] = s;
  __syncthreads();
  float st = 0.f;
#pragma unroll
  for (int k = 0; k < 8; k++) st += redB[k];
  const float inv = 1.f / st;
  for (int j = tid; j < jend; j += 256) row[j] = (j <= jm) ? buf[j]*inv : 0.f;
}

// ---------------- O = P @ V (k bounded by causal tile) ----------------
__global__ __launch_bounds__(256) void k_pv()
{
  const int h = blockIdx.z, bm = blockIdx.y;
  __shared__ __align__(16) float As[8*128];
  __shared__ __align__(16) float Bs[8*128];
  float acc[8][8] = {};
  const int m0 = bm * 128;
  const int kend = (bm + 1) * 128;
  sgemm_tile<false>(acc, g_P + (size_t)h*SS*SS, SS, nullptr, m0,
                    g_V + (size_t)(h>>2)*SS*HD, HD, 0, 0, kend, As, Bs);
  const int tx = threadIdx.x & 15, ty = threadIdx.x >> 4;
  const int row0 = m0 + ty*8, col0 = tx*8;
#pragma unroll
  for (int i = 0; i < 8; i++) {
    float* cp = g_oc + (size_t)(row0+i)*DM + h*HD + col0;
    float4 a, b;
    a.x = acc[i][0]; a.y = acc[i][1]; a.z = acc[i][2]; a.w = acc[i][3];
    b.x = acc[i][4]; b.y = acc[i][5]; b.z = acc[i][6]; b.w = acc[i][7];
    *(float4*)cp = a; *(float4*)(cp+4) = b;
  }
}

// ---------------- res2 = g_oc @ wo + bo + hidden ----------------
__global__ __launch_bounds__(256) void k_oproj(const float* __restrict__ W,
    const float* __restrict__ bias, const float* __restrict__ resid)
{
  __shared__ __align__(16) float As[8*128];
  __shared__ __align__(16) float Bs[8*128];
  float acc[8][8] = {};
  const int m0 = blockIdx.y * 128, n0 = blockIdx.x * 128;
  sgemm_tile<false>(acc, g_oc, DM, nullptr, m0, W, DM, n0, 0, DM, As, Bs);
  const int tx = threadIdx.x & 15, ty = threadIdx.x >> 4;
  const int row0 = m0 + ty*8, col0 = n0 + tx*8;
#pragma unroll
  for (int i = 0; i < 8; i++) {
    const float* rp = resid + (size_t)(row0+i)*DM + col0;
    float4 r0 = *(const float4*)rp;
    float4 r1 = *(const float4*)(rp+4);
    float* cp = g_res2 + (size_t)(row0+i)*DM + col0;
    float4 a, b;
    a.x = acc[i][0]+bias[col0+0]+r0.x; a.y = acc[i][1]+bias[col0+1]+r0.y;
    a.z = acc[i][2]+bias[col0+2]+r0.z; a.w = acc[i][3]+bias[col0+3]+r0.w;
    b.x = acc[i][4]+bias[col0+4]+r1.x; b.y = acc[i][5]+bias[col0+5]+r1.y;
    b.z = acc[i][6]+bias[col0+6]+r1.z; b.w = acc[i][7]+bias[col0+7]+r1.w;
    *(float4*)cp = a; *(float4*)(cp+4) = b;
  }
}

__global__ __launch_bounds__(256) void k_copyres(float* __restrict__ dst)
{
  const int i = blockIdx.x * 256 + threadIdx.x;           // float4 index
  ((float4*)dst)[i] = ((const float4*)g_res2)[i];
}

// ---------------- router + sparsemixer ----------------
__global__ void k_zero() { if (threadIdx.x < NE) g_cnt[threadIdx.x] = 0; }

__global__ __launch_bounds__(256) void k_router(const float* __restrict__ gw)
{
  const int t = blockIdx.x;
  const float* x = g_xln + (size_t)t * DM;
  float acc[NE];
#pragma unroll
  for (int e = 0; e < NE; e++) acc[e] = 0.f;
  for (int d = threadIdx.x; d < DM; d += 256) {
    const float xv = x[d];
    const float* gr = gw + d * NE;
#pragma unroll
    for (int e = 0; e < NE; e++) acc[e] += xv * gr[e];
  }
  __shared__ float sh[NE][8];
  const int lane = threadIdx.x & 31, w = threadIdx.x >> 5;
#pragma unroll
  for (int e = 0; e < NE; e++) {
    float v = acc[e];
    for (int o = 16; o; o >>= 1) v += __shfl_xor_sync(0xffffffffu, v, o);
    if (lane == 0) sh[e][w] = v;
  }
  __syncthreads();
  if (threadIdx.x == 0) {
    float s[NE];
#pragma unroll
    for (int e = 0; e < NE; e++) {
      float v = 0.f;
#pragma unroll
      for (int k = 0; k < 8; k++) v += sh[e][k];
      s[e] = v;
    }
    const float teps = 0.02f;   // 2 * jitter_eps
    int i1 = 0;
    for (int e = 1; e < NE; e++) if (s[e] > s[i1]) i1 = e;
    const float mx1 = s[i1];
    float den = 0.f;
    for (int e = 0; e < NE; e++) {
      const float f = fmaxf(fabsf(s[e]), mx1);
      if (!((mx1 - s[e]) / f > teps)) den += expf(s[e] - mx1);
    }
    const float w1 = 1.f / den;
    int i2 = -1; float mx2 = -INFINITY;
    for (int e = 0; e < NE; e++) if (e != i1 && s[e] > mx2) { mx2 = s[e]; i2 = e; }
    float den2 = 0.f;
    for (int e = 0; e < NE; e++) {
      if (e == i1) continue;
      const float f = fmaxf(fabsf(s[e]), mx2);
      if (!((mx2 - s[e]) / f > teps)) den2 += expf(s[e] - mx2);
    }
    const float w2 = 1.f / den2;
    g_topw[t*2] = w1; g_topw[t*2+1] = w2;
    g_topid[t*2] = i1; g_topid[t*2+1] = i2;
    atomicAdd(&g_cnt[i1], 1); atomicAdd(&g_cnt[i2], 1);
  }
}

__global__ __launch_bounds__(256) void k_setup()
{
  const int tid = threadIdx.x;
  if (tid == 0) {
    for (int t = 0; t < MAXTILES; t++) g_tileexp[t] = -1;
    int o = 0;
    for (int e = 0; e < NE; e++) {
      g_off[e] = o;
      const int tiles = (g_cnt[e] + 127) >> 7;
      for (int t = 0; t < tiles; t++) g_tileexp[(o >> 7) + t] = e;
      o += tiles << 7;
    }
  }
  for (int i = tid; i < MAXROWS; i += 256) { g_rows[i] = 0; g_wv[i] = 0.f; }
  if (tid < NE) g_cnt2[tid] = 0;
}

__global__ __launch_bounds__(256) void k_scatter()
{
  const int t = blockIdx.x * 256 + threadIdx.x;
  if (t >= SS) return;
#pragma unroll
  for (int j = 0; j < 2; j++) {
    const int e = g_topid[t*2+j];
    const int pos = g_off[e] + atomicAdd(&g_cnt2[e], 1);
    g_rows[pos] = t;
    g_wv[pos] = g_topw[t*2+j];
    g_slot[t*2+j] = pos;
  }
}

// ---------------- MoE GEMMs ----------------
// EPI: 0 = plain store (gate), 1 = h = silu(prevC)*acc in place (up)
template<int EPI>
__global__ __launch_bounds__(256) void k_moe_gu(const float* __restrict__ Wall)
{
  const int e = g_tileexp[blockIdx.y];
  if (e < 0) return;
  __shared__ __align__(16) float As[8*128];
  __shared__ __align__(16) float Bs[8*128];
  float acc[8][8] = {};
  const int m0 = blockIdx.y * 128, n0 = blockIdx.x * 128;
  const float* B = Wall + (size_t)e * FF * DM;      // [FF, DM] row-major -> nt
  sgemm_tile<true>(acc, g_xln, DM, g_rows, m0, B, DM, n0, 0, DM, As, Bs);
  const int tx = threadIdx.x & 15, ty = threadIdx.x >> 4;
  const int row0 = m0 + ty*8, col0 = n0 + tx*8;
#pragma unroll
  for (int i = 0; i < 8; i++) {
    float* cp = g_gbuf + (size_t)(row0+i)*FF + col0;
    if (EPI == 0) {
      float4 a, b;
      a.x = acc[i][0]; a.y = acc[i][1]; a.z = acc[i][2]; a.w = acc[i][3];
      b.x = acc[i][4]; b.y = acc[i][5]; b.z = acc[i][6]; b.w = acc[i][7];
      *(float4*)cp = a; *(float4*)(cp+4) = b;
    } else {
      float4 g0 = *(const float4*)cp;
      float4 g1 = *(const float4*)(cp+4);
      float4 a, b;
      a.x = (g0.x/(1.f+expf(-g0.x))) * acc[i][0];
      a.y = (g0.y/(1.f+expf(-g0.y))) * acc[i][1];
      a.z = (g0.z/(1.f+expf(-g0.z))) * acc[i][2];
      a.w = (g0.w/(1.f+expf(-g0.w))) * acc[i][3];
      b.x = (g1.x/(1.f+expf(-g1.x))) * acc[i][4];
      b.y = (g1.y/(1.f+expf(-g1.y))) * acc[i][5];
      b.z = (g1.z/(1.f+expf(-g1.z))) * acc[i][6];
      b.w = (g1.w/(1.f+expf(-g1.w))) * acc[i][7];
      *(float4*)cp = a; *(float4*)(cp+4) = b;
    }
  }
}

__global__ __launch_bounds__(256) void k_moe_down(const float* __restrict__ Wall)
{
  const int e = g_tileexp[blockIdx.y];
  if (e < 0) return;
  __shared__ __align__(16) float As[8*128];
  __shared__ __align__(16) float Bs[8*128];
  float acc[8][8] = {};
  const int m0 = blockIdx.y * 128, n0 = blockIdx.x * 128;
  const float* B = Wall + (size_t)e * DM * FF;      // [DM, FF] row-major -> nt (K=FF)
  sgemm_tile<true>(acc, g_gbuf, FF, nullptr, m0, B, FF, n0, 0, FF, As, Bs);
  const int tx = threadIdx.x & 15, ty = threadIdx.x >> 4;
  const int row0 = m0 + ty*8, col0 = n0 + tx*8;
#pragma unroll
  for (int i = 0; i < 8; i++) {
    const float wv = g_wv[row0+i];
    float* cp = g_dout + (size_t)(row0+i)*DM + col0;
    float4 a, b;
    a.x = acc[i][0]*wv; a.y = acc[i][1]*wv; a.z = acc[i][2]*wv; a.w = acc[i][3]*wv;
    b.x = acc[i][4]*wv; b.y = acc[i][5]*wv; b.z = acc[i][6]*wv; b.w = acc[i][7]*wv;
    *(float4*)cp = a; *(float4*)(cp+4) = b;
  }
}

__global__ __launch_bounds__(256) void k_combine(float* __restrict__ out)
{
  const int t = blockIdx.y;
  const int d = blockIdx.x * 256 + threadIdx.x;
  const int s0 = g_slot[t*2], s1 = g_slot[t*2+1];
  out[(size_t)t*DM + d] = g_dout[(size_t)s0*DM + d] + g_dout[(size_t)s1*DM + d];
}

// ---------------- launch ----------------
extern "C" void kernel_launch(void* const* d_in, const int* in_sizes, int n_in,
                              void* d_out, int out_size)
{
  const float* hidden = (const float*)d_in[0];
  const float* cosb   = (const float*)d_in[1];
  const float* sinb   = (const float*)d_in[2];
  const float* ln1w   = (const float*)d_in[3];
  const float* ln1b   = (const float*)d_in[4];
  const float* ln2w   = (const float*)d_in[5];
  const float* ln2b   = (const float*)d_in[6];
  const float* wqkv   = (const float*)d_in[7];
  const float* bqkv   = (const float*)d_in[8];
  const float* wo     = (const float*)d_in[9];
  const float* bo     = (const float*)d_in[10];
  const float* gatew  = (const float*)d_in[11];
  const float* wgate  = (const float*)d_in[12];
  const float* wup    = (const float*)d_in[13];
  const float* wdown  = (const float*)d_in[14];
  float* out = (float*)d_out;

  k_zero<<<1, 32>>>();
  k_ln1<<<SS, 256>>>(hidden, ln1w, ln1b);
  k_gemm_qkv<<<dim3(QKVN/128, SS/128), 256>>>(wqkv, bqkv);
  k_rope<<<dim3(QKVN/256, SS), 256>>>(cosb, sinb);
  k_scores<<<dim3(SS/128, SS/128, NH), 256>>>(0.08838834764831845f);
  k_softmax<<<dim3(SS, NH), 256>>>();
  k_pv<<<dim3(1, SS/128, NH), 256>>>();
  k_oproj<<<dim3(DM/128, SS/128), 256>>>(wo, bo, hidden);
  if (out_size >= 2 * SS * DM)
    k_copyres<<<(SS*DM/4)/256, 256>>>(out + (size_t)SS*DM);
  k_ln2<<<SS, 256>>>(ln2w, ln2b);
  k_router<<<SS, 256>>>(gatew);
  k_setup<<<1, 256>>>();
  k_scatter<<<(SS + 255)/256, 256>>>();
  k_moe_gu<0><<<dim3(FF/128, MAXTILES), 256>>>(wgate);
  k_moe_gu<1><<<dim3(FF/128, MAXTILES), 256>>>(wup);
  k_moe_down<<<dim3(DM/128, MAXTILES), 256>>>(wdown);
  k_combine<<<dim3(DM/256, SS), 256>>>(out);
}

// round 3
// speedup vs baseline: 2.2005x; 2.2005x over previous
#include <cuda_runtime.h>
#include <math.h>

#define SS   2048
#define DM   2048
#define NH   16
#define NKV  4
#define HD   128
#define NE   8
#define FF   4096
#define QKVN 3072
#define MAXROWS 5120
#define MAXTILES 40

// ---------------- scratch ----------------
__device__ float g_xln[SS*DM];
__device__ float g_qkv[SS*QKVN];
__device__ float g_Q[NH*SS*HD];
__device__ float g_K[NKV*SS*HD];
__device__ float g_V[NKV*SS*HD];
__device__ float g_P[67108864];
__device__ float g_oc[SS*DM];
__device__ float g_res2[SS*DM];
__device__ float g_gbuf[MAXROWS*FF];
__device__ float g_dout[MAXROWS*DM];
__device__ float g_topw[SS*2];
__device__ int   g_topid[SS*2];
__device__ int   g_cnt[NE];
__device__ int   g_cnt2[NE];
__device__ int   g_off[NE];
__device__ int   g_rows[MAXROWS];
__device__ float g_wv[MAXROWS];
__device__ int   g_slot[SS*2];
__device__ int   g_tileexp[MAXTILES];

__device__ __forceinline__ unsigned f2tf(float x) {
  unsigned r;
  asm("cvt.rna.tf32.f32 %0, %1;" : "=r"(r) : "f"(x));
  return r;
}

#define MMA_TF32(ACC, A0,A1,A2,A3, B0,B1) \
  asm volatile( \
    "mma.sync.aligned.m16n8k8.row.col.f32.tf32.tf32.f32 " \
    "{%0,%1,%2,%3}, {%4,%5,%6,%7}, {%8,%9}, {%0,%1,%2,%3};" \
    : "+f"((ACC)[0]), "+f"((ACC)[1]), "+f"((ACC)[2]), "+f"((ACC)[3]) \
    : "r"(A0), "r"(A1), "r"(A2), "r"(A3), "r"(B0), "r"(B1))

// ---------------- TF32 MMA tile core, BK=8 ----------------
// CTA 128x128, 256 threads = 8 warps (2 M x 4 N), warp tile 64x32.
// SPLIT=3: 3xTF32 (hi/lo) -> ~fp32 precision. SPLIT=1: plain TF32.
// Fragment-order smem:
//   A word [mt][e][lane], idx = mt*128 + e*32 + lane   (1024 words/buf)
//   B word [nt][e][lane], idx = nt*64  + e*32 + lane   (1024 words/buf)
template<bool BT, int SPLIT>
__device__ __forceinline__ void tf32_tile8(
    float (&acc)[4][4][4],
    const float* __restrict__ A, int lda, const int* __restrict__ rowmap, int m0,
    const float* __restrict__ B, int ldb, int n0,
    int kbeg, int kend,
    float* __restrict__ As, float* __restrict__ Asl,
    float* __restrict__ Bs, float* __restrict__ Bsl)
{
  const int tid = threadIdx.x, lane = tid & 31, warp = tid >> 5;
  const int wm = warp & 1, wn = warp >> 1;

  const int am = tid >> 1, akq = (tid & 1) << 2;
  const int ar = rowmap ? rowmap[m0 + am] : (m0 + am);
  const float* aptr = A + (size_t)ar * lda + akq;
  const int asto = (am>>4)*128 + (((am&8)>>3) | ((akq&4)>>1))*32 + (am&7)*4;

  const float* bptr;
  int bn, bkq;
  if (BT) { bn = tid >> 1;  bkq = (tid & 1) << 2; bptr = B + (size_t)(n0 + bn)*ldb + bkq; }
  else    { bn = tid & 127; bkq = (tid >> 7) << 2; bptr = B + n0 + bn; }
  const int bsto = (bn>>3)*64 + ((bkq&4)>>2)*32 + (bn&7)*4;

  int aro[4], bro[4];
#pragma unroll
  for (int i = 0; i < 4; i++) aro[i] = (wm*4 + i)*128 + lane;
#pragma unroll
  for (int j = 0; j < 4; j++) bro[j] = (wn*4 + j)*64 + lane;

  float4 aS, bS;
  auto load = [&](int k0) {
    aS = *(const float4*)(aptr + k0);
    if (BT) {
      bS = *(const float4*)(bptr + k0);
    } else {
      const float* p = bptr + (size_t)(k0 + bkq) * ldb;
      bS.x = p[0]; bS.y = p[ldb]; bS.z = p[2*ldb]; bS.w = p[3*ldb];
    }
  };
  auto store = [&](int buf) {
    uint4 h;
    h.x = f2tf(aS.x); h.y = f2tf(aS.y); h.z = f2tf(aS.z); h.w = f2tf(aS.w);
    *(uint4*)(As + buf*1024 + asto) = h;
    if (SPLIT == 3) {
      uint4 l;
      l.x = f2tf(aS.x - __uint_as_float(h.x));
      l.y = f2tf(aS.y - __uint_as_float(h.y));
      l.z = f2tf(aS.z - __uint_as_float(h.z));
      l.w = f2tf(aS.w - __uint_as_float(h.w));
      *(uint4*)(Asl + buf*1024 + asto) = l;
    }
    uint4 hb;
    hb.x = f2tf(bS.x); hb.y = f2tf(bS.y); hb.z = f2tf(bS.z); hb.w = f2tf(bS.w);
    *(uint4*)(Bs + buf*1024 + bsto) = hb;
    if (SPLIT == 3) {
      uint4 lb;
      lb.x = f2tf(bS.x - __uint_as_float(hb.x));
      lb.y = f2tf(bS.y - __uint_as_float(hb.y));
      lb.z = f2tf(bS.z - __uint_as_float(hb.z));
      lb.w = f2tf(bS.w - __uint_as_float(hb.w));
      *(uint4*)(Bsl + buf*1024 + bsto) = lb;
    }
  };
  auto comp = [&](int buf) {
    unsigned ah[4][4], bh[4][2];
    unsigned al[4][4], bl[4][2];
#pragma unroll
    for (int i = 0; i < 4; i++)
#pragma unroll
      for (int e = 0; e < 4; e++) {
        ah[i][e] = __float_as_uint(As[buf*1024 + aro[i] + e*32]);
        if (SPLIT == 3) al[i][e] = __float_as_uint(Asl[buf*1024 + aro[i] + e*32]);
      }
#pragma unroll
    for (int j = 0; j < 4; j++)
#pragma unroll
      for (int e = 0; e < 2; e++) {
        bh[j][e] = __float_as_uint(Bs[buf*1024 + bro[j] + e*32]);
        if (SPLIT == 3) bl[j][e] = __float_as_uint(Bsl[buf*1024 + bro[j] + e*32]);
      }
#pragma unroll
    for (int i = 0; i < 4; i++)
#pragma unroll
      for (int j = 0; j < 4; j++) {
        if (SPLIT == 3) {
          MMA_TF32(acc[i][j], al[i][0],al[i][1],al[i][2],al[i][3], bh[j][0],bh[j][1]);
          MMA_TF32(acc[i][j], ah[i][0],ah[i][1],ah[i][2],ah[i][3], bl[j][0],bl[j][1]);
        }
        MMA_TF32(acc[i][j], ah[i][0],ah[i][1],ah[i][2],ah[i][3], bh[j][0],bh[j][1]);
      }
  };

  load(kbeg);
  store(0);
  __syncthreads();
  int buf = 0;
  for (int k0 = kbeg + 8; k0 < kend; k0 += 8) {
    load(k0);
    comp(buf);
    store(buf ^ 1);
    __syncthreads();
    buf ^= 1;
  }
  comp(buf);
}

#define EPI_SETUP() \
  const int lane = threadIdx.x & 31, warp = threadIdx.x >> 5; \
  const int wm = warp & 1, wn = warp >> 1; \
  const int g = lane >> 2, tg = lane & 3;

#define SMEM_SPLIT3 \
  __shared__ __align__(16) float As[2*1024];  \
  __shared__ __align__(16) float Asl[2*1024]; \
  __shared__ __align__(16) float Bs[2*1024];  \
  __shared__ __align__(16) float Bsl[2*1024];

#define SMEM_SPLIT1 \
  __shared__ __align__(16) float As[2*1024];  \
  __shared__ __align__(16) float Bs[2*1024];

// ---------------- LayerNorm ----------------
__device__ __forceinline__ void ln_body(const float* __restrict__ x,
    const float* __restrict__ w, const float* __restrict__ b, float* __restrict__ y)
{
  float s = 0.f, ss = 0.f;
  for (int d = threadIdx.x*4; d < DM; d += 1024) {
    float4 v = *(const float4*)(x + d);
    s  += v.x + v.y + v.z + v.w;
    ss += v.x*v.x + v.y*v.y + v.z*v.z + v.w*v.w;
  }
  __shared__ float shA[8], shB[8];
  const int lane = threadIdx.x & 31, wi = threadIdx.x >> 5;
  for (int o = 16; o; o >>= 1) { s += __shfl_xor_sync(0xffffffffu, s, o); ss += __shfl_xor_sync(0xffffffffu, ss, o); }
  if (lane == 0) { shA[wi] = s; shB[wi] = ss; }
  __syncthreads();
  float st = 0.f, sst = 0.f;
#pragma unroll
  for (int k = 0; k < 8; k++) { st += shA[k]; sst += shB[k]; }
  const float mean = st / (float)DM;
  const float var  = sst / (float)DM - mean*mean;
  const float rstd = rsqrtf(var + 1e-5f);
  for (int d = threadIdx.x*4; d < DM; d += 1024) {
    float4 v = *(const float4*)(x + d);
    float4 wv = *(const float4*)(w + d);
    float4 bv = *(const float4*)(b + d);
    float4 o;
    o.x = (v.x-mean)*rstd*wv.x + bv.x;
    o.y = (v.y-mean)*rstd*wv.y + bv.y;
    o.z = (v.z-mean)*rstd*wv.z + bv.z;
    o.w = (v.w-mean)*rstd*wv.w + bv.w;
    *(float4*)(y + d) = o;
  }
}

__global__ __launch_bounds__(256) void k_ln1(const float* __restrict__ hidden,
    const float* __restrict__ w, const float* __restrict__ b)
{
  const int row = blockIdx.x;
  ln_body(hidden + (size_t)row*DM, w, b, g_xln + (size_t)row*DM);
}

__global__ __launch_bounds__(256) void k_ln2(const float* __restrict__ w, const float* __restrict__ b)
{
  const int row = blockIdx.x;
  ln_body(g_res2 + (size_t)row*DM, w, b, g_xln + (size_t)row*DM);
}

// ---------------- QKV GEMM (3xTF32) ----------------
__global__ __launch_bounds__(256) void t_gemm_qkv(const float* __restrict__ W,
                                                  const float* __restrict__ bias)
{
  SMEM_SPLIT3;
  float acc[4][4][4] = {};
  const int m0 = blockIdx.y * 128, n0 = blockIdx.x * 128;
  tf32_tile8<false,3>(acc, g_xln, DM, nullptr, m0, W, QKVN, n0, 0, DM, As, Asl, Bs, Bsl);
  EPI_SETUP();
#pragma unroll
  for (int i = 0; i < 4; i++)
#pragma unroll
    for (int j = 0; j < 4; j++) {
      const int row = m0 + wm*64 + i*16 + g;
      const int col = n0 + wn*32 + j*8 + tg*2;
      const float b0 = bias[col], b1 = bias[col+1];
      *(float2*)(g_qkv + (size_t)row*QKVN + col)     = make_float2(acc[i][j][0]+b0, acc[i][j][1]+b1);
      *(float2*)(g_qkv + (size_t)(row+8)*QKVN + col) = make_float2(acc[i][j][2]+b0, acc[i][j][3]+b1);
    }
}

// ---------------- RoPE + split ----------------
__global__ __launch_bounds__(256) void k_rope(const float* __restrict__ cosb,
                                              const float* __restrict__ sinb)
{
  const int s = blockIdx.y;
  const int col = blockIdx.x * 256 + threadIdx.x;
  const float* qrow = g_qkv + (size_t)s * QKVN;
  const float x = qrow[col];
  if (col < NH*HD) {
    const int h = col >> 7, d = col & 127;
    const float c = cosb[s*HD+d], sn = sinb[s*HD+d];
    const float p = (d < 64) ? -qrow[col+64] : qrow[col-64];
    g_Q[((size_t)h*SS + s)*HD + d] = x*c + p*sn;
  } else if (col < (NH+NKV)*HD) {
    const int cc = col - NH*HD;
    const int h = cc >> 7, d = cc & 127;
    const float c = cosb[s*HD+d], sn = sinb[s*HD+d];
    const float p = (d < 64) ? -qrow[col+64] : qrow[col-64];
    g_K[((size_t)h*SS + s)*HD + d] = x*c + p*sn;
  } else {
    const int cc = col - (NH+NKV)*HD;
    const int h = cc >> 7, d = cc & 127;
    g_V[((size_t)h*SS + s)*HD + d] = x;
  }
}

// ---------------- scores (3xTF32) ----------------
__global__ __launch_bounds__(256) void t_scores(float scale)
{
  if (blockIdx.x > blockIdx.y) return;
  const int h = blockIdx.z;
  SMEM_SPLIT3;
  float acc[4][4][4] = {};
  const int m0 = blockIdx.y * 128, n0 = blockIdx.x * 128;
  tf32_tile8<true,3>(acc, g_Q + (size_t)h*SS*HD, HD, nullptr, m0,
                     g_K + (size_t)(h>>2)*SS*HD, HD, n0, 0, HD, As, Asl, Bs, Bsl);
  EPI_SETUP();
  float* Ph = g_P + (size_t)h*SS*SS;
#pragma unroll
  for (int i = 0; i < 4; i++)
#pragma unroll
    for (int j = 0; j < 4; j++) {
      const int row = m0 + wm*64 + i*16 + g;
      const int col = n0 + wn*32 + j*8 + tg*2;
      *(float2*)(Ph + (size_t)row*SS + col)     = make_float2(acc[i][j][0]*scale, acc[i][j][1]*scale);
      *(float2*)(Ph + (size_t)(row+8)*SS + col) = make_float2(acc[i][j][2]*scale, acc[i][j][3]*scale);
    }
}

// ---------------- softmax ----------------
__global__ __launch_bounds__(256) void k_softmax()
{
  const int i = blockIdx.x, h = blockIdx.y;
  float* row = g_P + ((size_t)h*SS + i)*SS;
  const int jm = i;
  const int jend = ((i >> 7) + 1) << 7;
  __shared__ float buf[2048];
  __shared__ float redA[8], redB[8];
  const int tid = threadIdx.x;
  float mx = -1e30f;
  for (int j = tid; j <= jm; j += 256) { float v = row[j]; buf[j] = v; mx = fmaxf(mx, v); }
  for (int o = 16; o; o >>= 1) mx = fmaxf(mx, __shfl_xor_sync(0xffffffffu, mx, o));
  if ((tid & 31) == 0) redA[tid >> 5] = mx;
  __syncthreads();
  float m = redA[0];
#pragma unroll
  for (int k = 1; k < 8; k++) m = fmaxf(m, redA[k]);
  float s = 0.f;
  for (int j = tid; j <= jm; j += 256) { float e = expf(buf[j] - m); buf[j] = e; s += e; }
  for (int o = 16; o; o >>= 1) s += __shfl_xor_sync(0xffffffffu, s, o);
  if ((tid & 31) == 0) redB[tid >> 5] = s;
  __syncthreads();
  float st = 0.f;
#pragma unroll
  for (int k = 0; k < 8; k++) st += redB[k];
  const float inv = 1.f / st;
  for (int j = tid; j < jend; j += 256) row[j] = (j <= jm) ? buf[j]*inv : 0.f;
}

// ---------------- PV (3xTF32) ----------------
__global__ __launch_bounds__(256) void t_pv()
{
  const int h = blockIdx.z, bm = blockIdx.y;
  SMEM_SPLIT3;
  float acc[4][4][4] = {};
  const int m0 = bm * 128;
  const int kend = (bm + 1) * 128;
  tf32_tile8<false,3>(acc, g_P + (size_t)h*SS*SS, SS, nullptr, m0,
                      g_V + (size_t)(h>>2)*SS*HD, HD, 0, 0, kend, As, Asl, Bs, Bsl);
  EPI_SETUP();
#pragma unroll
  for (int i = 0; i < 4; i++)
#pragma unroll
    for (int j = 0; j < 4; j++) {
      const int row = m0 + wm*64 + i*16 + g;
      const int col = wn*32 + j*8 + tg*2;
      *(float2*)(g_oc + (size_t)row*DM + h*HD + col)     = make_float2(acc[i][j][0], acc[i][j][1]);
      *(float2*)(g_oc + (size_t)(row+8)*DM + h*HD + col) = make_float2(acc[i][j][2], acc[i][j][3]);
    }
}

// ---------------- O proj + residual (3xTF32) ----------------
__global__ __launch_bounds__(256) void t_oproj(const float* __restrict__ W,
    const float* __restrict__ bias, const float* __restrict__ resid)
{
  SMEM_SPLIT3;
  float acc[4][4][4] = {};
  const int m0 = blockIdx.y * 128, n0 = blockIdx.x * 128;
  tf32_tile8<false,3>(acc, g_oc, DM, nullptr, m0, W, DM, n0, 0, DM, As, Asl, Bs, Bsl);
  EPI_SETUP();
#pragma unroll
  for (int i = 0; i < 4; i++)
#pragma unroll
    for (int j = 0; j < 4; j++) {
      const int row = m0 + wm*64 + i*16 + g;
      const int col = n0 + wn*32 + j*8 + tg*2;
      const float b0 = bias[col], b1 = bias[col+1];
      float2 r0 = *(const float2*)(resid + (size_t)row*DM + col);
      float2 r1 = *(const float2*)(resid + (size_t)(row+8)*DM + col);
      *(float2*)(g_res2 + (size_t)row*DM + col)     = make_float2(acc[i][j][0]+b0+r0.x, acc[i][j][1]+b1+r0.y);
      *(float2*)(g_res2 + (size_t)(row+8)*DM + col) = make_float2(acc[i][j][2]+b0+r1.x, acc[i][j][3]+b1+r1.y);
    }
}

__global__ __launch_bounds__(256) void k_copyres(float* __restrict__ dst)
{
  const int i = blockIdx.x * 256 + threadIdx.x;
  ((float4*)dst)[i] = ((const float4*)g_res2)[i];
}

// ---------------- router + sparsemixer ----------------
__global__ void k_zero() { if (threadIdx.x < NE) g_cnt[threadIdx.x] = 0; }

__global__ __launch_bounds__(256) void k_router(const float* __restrict__ gw)
{
  const int t = blockIdx.x;
  const float* x = g_xln + (size_t)t * DM;
  float acc[NE];
#pragma unroll
  for (int e = 0; e < NE; e++) acc[e] = 0.f;
  for (int d = threadIdx.x; d < DM; d += 256) {
    const float xv = x[d];
    const float* gr = gw + d * NE;
#pragma unroll
    for (int e = 0; e < NE; e++) acc[e] += xv * gr[e];
  }
  __shared__ float sh[NE][8];
  const int lane = threadIdx.x & 31, w = threadIdx.x >> 5;
#pragma unroll
  for (int e = 0; e < NE; e++) {
    float v = acc[e];
    for (int o = 16; o; o >>= 1) v += __shfl_xor_sync(0xffffffffu, v, o);
    if (lane == 0) sh[e][w] = v;
  }
  __syncthreads();
  if (threadIdx.x == 0) {
    float s[NE];
#pragma unroll
    for (int e = 0; e < NE; e++) {
      float v = 0.f;
#pragma unroll
      for (int k = 0; k < 8; k++) v += sh[e][k];
      s[e] = v;
    }
    const float teps = 0.02f;
    int i1 = 0;
    for (int e = 1; e < NE; e++) if (s[e] > s[i1]) i1 = e;
    const float mx1 = s[i1];
    float den = 0.f;
    for (int e = 0; e < NE; e++) {
      const float f = fmaxf(fabsf(s[e]), mx1);
      if (!((mx1 - s[e]) / f > teps)) den += expf(s[e] - mx1);
    }
    const float w1 = 1.f / den;
    int i2 = -1; float mx2 = -INFINITY;
    for (int e = 0; e < NE; e++) if (e != i1 && s[e] > mx2) { mx2 = s[e]; i2 = e; }
    float den2 = 0.f;
    for (int e = 0; e < NE; e++) {
      if (e == i1) continue;
      const float f = fmaxf(fabsf(s[e]), mx2);
      if (!((mx2 - s[e]) / f > teps)) den2 += expf(s[e] - mx2);
    }
    const float w2 = 1.f / den2;
    g_topw[t*2] = w1; g_topw[t*2+1] = w2;
    g_topid[t*2] = i1; g_topid[t*2+1] = i2;
    atomicAdd(&g_cnt[i1], 1); atomicAdd(&g_cnt[i2], 1);
  }
}

__global__ __launch_bounds__(256) void k_setup()
{
  const int tid = threadIdx.x;
  if (tid == 0) {
    for (int t = 0; t < MAXTILES; t++) g_tileexp[t] = -1;
    int o = 0;
    for (int e = 0; e < NE; e++) {
      g_off[e] = o;
      const int tiles = (g_cnt[e] + 127) >> 7;
      for (int t = 0; t < tiles; t++) g_tileexp[(o >> 7) + t] = e;
      o += tiles << 7;
    }
  }
  for (int i = tid; i < MAXROWS; i += 256) { g_rows[i] = 0; g_wv[i] = 0.f; }
  if (tid < NE) g_cnt2[tid] = 0;
}

__global__ __launch_bounds__(256) void k_scatter()
{
  const int t = blockIdx.x * 256 + threadIdx.x;
  if (t >= SS) return;
#pragma unroll
  for (int j = 0; j < 2; j++) {
    const int e = g_topid[t*2+j];
    const int pos = g_off[e] + atomicAdd(&g_cnt2[e], 1);
    g_rows[pos] = t;
    g_wv[pos] = g_topw[t*2+j];
    g_slot[t*2+j] = pos;
  }
}

// ---------------- MoE GEMMs (1xTF32) ----------------
template<int EPI>
__global__ __launch_bounds__(256) void t_moe_gu(const float* __restrict__ Wall)
{
  const int e = g_tileexp[blockIdx.y];
  if (e < 0) return;
  SMEM_SPLIT1;
  float acc[4][4][4] = {};
  const int m0 = blockIdx.y * 128, n0 = blockIdx.x * 128;
  const float* B = Wall + (size_t)e * FF * DM;
  tf32_tile8<true,1>(acc, g_xln, DM, g_rows, m0, B, DM, n0, 0, DM, As, nullptr, Bs, nullptr);
  EPI_SETUP();
#pragma unroll
  for (int i = 0; i < 4; i++)
#pragma unroll
    for (int j = 0; j < 4; j++) {
      const int row = m0 + wm*64 + i*16 + g;
      const int col = n0 + wn*32 + j*8 + tg*2;
      float* p0 = g_gbuf + (size_t)row*FF + col;
      float* p1 = g_gbuf + (size_t)(row+8)*FF + col;
      if (EPI == 0) {
        *(float2*)p0 = make_float2(acc[i][j][0], acc[i][j][1]);
        *(float2*)p1 = make_float2(acc[i][j][2], acc[i][j][3]);
      } else {
        float2 g0 = *(float2*)p0;
        float2 g1 = *(float2*)p1;
        float2 v0, v1;
        v0.x = (g0.x/(1.f+expf(-g0.x))) * acc[i][j][0];
        v0.y = (g0.y/(1.f+expf(-g0.y))) * acc[i][j][1];
        v1.x = (g1.x/(1.f+expf(-g1.x))) * acc[i][j][2];
        v1.y = (g1.y/(1.f+expf(-g1.y))) * acc[i][j][3];
        *(float2*)p0 = v0;
        *(float2*)p1 = v1;
      }
    }
}

__global__ __launch_bounds__(256) void t_moe_down(const float* __restrict__ Wall)
{
  const int e = g_tileexp[blockIdx.y];
  if (e < 0) return;
  SMEM_SPLIT1;
  float acc[4][4][4] = {};
  const int m0 = blockIdx.y * 128, n0 = blockIdx.x * 128;
  const float* B = Wall + (size_t)e * DM * FF;
  tf32_tile8<true,1>(acc, g_gbuf, FF, nullptr, m0, B, FF, n0, 0, FF, As, nullptr, Bs, nullptr);
  EPI_SETUP();
#pragma unroll
  for (int i = 0; i < 4; i++)
#pragma unroll
    for (int j = 0; j < 4; j++) {
      const int row = m0 + wm*64 + i*16 + g;
      const int col = n0 + wn*32 + j*8 + tg*2;
      const float w0 = g_wv[row], w1 = g_wv[row+8];
      *(float2*)(g_dout + (size_t)row*DM + col)     = make_float2(acc[i][j][0]*w0, acc[i][j][1]*w0);
      *(float2*)(g_dout + (size_t)(row+8)*DM + col) = make_float2(acc[i][j][2]*w1, acc[i][j][3]*w1);
    }
}

__global__ __launch_bounds__(256) void k_combine(float* __restrict__ out)
{
  const int t = blockIdx.y;
  const int d = blockIdx.x * 256 + threadIdx.x;
  const int s0 = g_slot[t*2], s1 = g_slot[t*2+1];
  out[(size_t)t*DM + d] = g_dout[(size_t)s0*DM + d] + g_dout[(size_t)s1*DM + d];
}

// ---------------- launch ----------------
extern "C" void kernel_launch(void* const* d_in, const int* in_sizes, int n_in,
                              void* d_out, int out_size)
{
  const float* hidden = (const float*)d_in[0];
  const float* cosb   = (const float*)d_in[1];
  const float* sinb   = (const float*)d_in[2];
  const float* ln1w   = (const float*)d_in[3];
  const float* ln1b   = (const float*)d_in[4];
  const float* ln2w   = (const float*)d_in[5];
  const float* ln2b   = (const float*)d_in[6];
  const float* wqkv   = (const float*)d_in[7];
  const float* bqkv   = (const float*)d_in[8];
  const float* wo     = (const float*)d_in[9];
  const float* bo     = (const float*)d_in[10];
  const float* gatew  = (const float*)d_in[11];
  const float* wgate  = (const float*)d_in[12];
  const float* wup    = (const float*)d_in[13];
  const float* wdown  = (const float*)d_in[14];
  float* out = (float*)d_out;

  k_zero<<<1, 32>>>();
  k_ln1<<<SS, 256>>>(hidden, ln1w, ln1b);
  t_gemm_qkv<<<dim3(QKVN/128, SS/128), 256>>>(wqkv, bqkv);
  k_rope<<<dim3(QKVN/256, SS), 256>>>(cosb, sinb);
  t_scores<<<dim3(SS/128, SS/128, NH), 256>>>(0.08838834764831845f);
  k_softmax<<<dim3(SS, NH), 256>>>();
  t_pv<<<dim3(1, SS/128, NH), 256>>>();
  t_oproj<<<dim3(DM/128, SS/128), 256>>>(wo, bo, hidden);
  if (out_size >= 2 * SS * DM)
    k_copyres<<<(SS*DM/4)/256, 256>>>(out + (size_t)SS*DM);
  k_ln2<<<SS, 256>>>(ln2w, ln2b);
  k_router<<<SS, 256>>>(gatew);
  k_setup<<<1, 256>>>();
  k_scatter<<<(SS + 255)/256, 256>>>();
  t_moe_gu<0><<<dim3(FF/128, MAXTILES), 256>>>(wgate);
  t_moe_gu<1><<<dim3(FF/128, MAXTILES), 256>>>(wup);
  t_moe_down<<<dim3(DM/128, MAXTILES), 256>>>(wdown);
  k_combine<<<dim3(DM/256, SS), 256>>>(out);
}

// round 4
// speedup vs baseline: 2.5775x; 1.1714x over previous
#include <cuda_runtime.h>
#include <cuda_fp16.h>
#include <math.h>

#define SS   2048
#define DM   2048
#define NH   16
#define NKV  4
#define HD   128
#define NE   8
#define FF   4096
#define QKVN 3072
#define MAXROWS 5120
#define MAXTILES 40

// ---------------- scratch ----------------
__device__ float g_xln[SS*DM];
__device__ float g_qkv[SS*QKVN];
__device__ float g_Q[NH*SS*HD];
__device__ float g_K[NKV*SS*HD];
__device__ float g_V[NKV*SS*HD];
__device__ float g_P[67108864];
__device__ float g_oc[SS*DM];
__device__ float g_res2[SS*DM];
__device__ float g_gbuf[MAXROWS*FF];
__device__ float g_dout[MAXROWS*DM];
__device__ float g_topw[SS*2];
__device__ int   g_topid[SS*2];
__device__ int   g_cnt[NE];
__device__ int   g_cnt2[NE];
__device__ int   g_off[NE];
__device__ int   g_rows[MAXROWS];
__device__ float g_wv[MAXROWS];
__device__ int   g_slot[SS*2];
__device__ int   g_tileexp[MAXTILES];

// ================= fp16-split (hi/lo) MMA tile, BK=16 =================
// CTA 128x128, 256 threads = 8 warps (2 M x 4 N), warp tile 64x32,
// m16n8k16 fp16 mma, fp32 accum. Three products: lo*hi + hi*lo + hi*hi.
// Fragment-order smem (packed half2 words, u32):
//   A word [mt(8)][e(4)][lane(32)] : e = 2*(k&8)/8 + (m&8)/8,
//                                    lane = (m&7)*4 + ((k&7)>>1)
//   B word [nt(16)][e(2)][lane(32)]: e = (k&8)/8, lane = (n&7)*4 + ((k&7)>>1)

#define MMA_F16(ACC, A0,A1,A2,A3, B0,B1) \
  asm volatile("mma.sync.aligned.m16n8k16.row.col.f32.f16.f16.f32 " \
    "{%0,%1,%2,%3}, {%4,%5,%6,%7}, {%8,%9}, {%0,%1,%2,%3};" \
    : "+f"((ACC)[0]),"+f"((ACC)[1]),"+f"((ACC)[2]),"+f"((ACC)[3]) \
    : "r"(A0),"r"(A1),"r"(A2),"r"(A3),"r"(B0),"r"(B1))

__device__ __forceinline__ void cvt2(float x, float y, unsigned &h, unsigned &l) {
  __half hx = __float2half_rn(x), hy = __float2half_rn(y);
  __half lx = __float2half_rn(x - __half2float(hx));
  __half ly = __float2half_rn(y - __half2float(hy));
  h = (unsigned)__half_as_ushort(hx) | ((unsigned)__half_as_ushort(hy) << 16);
  l = (unsigned)__half_as_ushort(lx) | ((unsigned)__half_as_ushort(ly) << 16);
}

template<bool BT>
__device__ __forceinline__ void f16_tile16(
    float (&acc)[4][4][4],
    const float* __restrict__ A, int lda, int m0,
    const float* __restrict__ B, int ldb, int n0,
    int kbeg, int kend,
    unsigned* __restrict__ Ah, unsigned* __restrict__ Al,
    unsigned* __restrict__ Bh, unsigned* __restrict__ Bl)
{
  const int tid = threadIdx.x, lane = tid & 31, warp = tid >> 5;
  const int wm = warp & 1, wn = warp >> 1;

  const float* aptr[2]; int aidx[2];
#pragma unroll
  for (int it = 0; it < 2; it++) {
    int q = tid + it*256;
    int m = q >> 2, kq = (q & 3) << 2;
    aptr[it] = A + (size_t)(m0 + m) * lda + kq;
    aidx[it] = (m>>4)*128 + (((kq&8)>>2) | ((m&8)>>3))*32 + (m&7)*4 + ((kq&4)>>1);
  }
  const float* bptr[2]; int bidx[2]; int bkq[2];
#pragma unroll
  for (int it = 0; it < 2; it++) {
    int q = tid + it*256;
    int n, kq;
    if (BT) { n = q >> 2;  kq = (q & 3) << 2; }
    else    { n = q & 127; kq = (q >> 7) << 2; }
    bkq[it] = kq;
    bptr[it] = BT ? (B + (size_t)(n0 + n) * ldb + kq) : (B + n0 + n);
    bidx[it] = (n>>3)*64 + ((kq&8)>>3)*32 + (n&7)*4 + ((kq&4)>>1);
  }

  float4 av[2], bv[2];
  auto load = [&](int k0) {
#pragma unroll
    for (int it = 0; it < 2; it++) {
      av[it] = *(const float4*)(aptr[it] + k0);
      if (BT) {
        bv[it] = *(const float4*)(bptr[it] + k0);
      } else {
        const float* p = bptr[it] + (size_t)(k0 + bkq[it]) * ldb;
        bv[it].x = p[0]; bv[it].y = p[ldb]; bv[it].z = p[2*ldb]; bv[it].w = p[3*ldb];
      }
    }
  };
  auto store = [&](int buf) {
#pragma unroll
    for (int it = 0; it < 2; it++) {
      unsigned h0,l0,h1,l1;
      cvt2(av[it].x, av[it].y, h0, l0);
      cvt2(av[it].z, av[it].w, h1, l1);
      *(uint2*)(Ah + buf*1024 + aidx[it]) = make_uint2(h0, h1);
      *(uint2*)(Al + buf*1024 + aidx[it]) = make_uint2(l0, l1);
      cvt2(bv[it].x, bv[it].y, h0, l0);
      cvt2(bv[it].z, bv[it].w, h1, l1);
      *(uint2*)(Bh + buf*1024 + bidx[it]) = make_uint2(h0, h1);
      *(uint2*)(Bl + buf*1024 + bidx[it]) = make_uint2(l0, l1);
    }
  };
  auto comp = [&](int buf) {
    unsigned ah[4][4], al[4][4], bh[4][2], bl[4][2];
#pragma unroll
    for (int i = 0; i < 4; i++)
#pragma unroll
      for (int e = 0; e < 4; e++) {
        int off = buf*1024 + (wm*4 + i)*128 + e*32 + lane;
        ah[i][e] = Ah[off];
        al[i][e] = Al[off];
      }
#pragma unroll
    for (int j = 0; j < 4; j++)
#pragma unroll
      for (int e = 0; e < 2; e++) {
        int off = buf*1024 + (wn*4 + j)*64 + e*32 + lane;
        bh[j][e] = Bh[off];
        bl[j][e] = Bl[off];
      }
#pragma unroll
    for (int i = 0; i < 4; i++)
#pragma unroll
      for (int j = 0; j < 4; j++) {
        MMA_F16(acc[i][j], al[i][0],al[i][1],al[i][2],al[i][3], bh[j][0],bh[j][1]);
        MMA_F16(acc[i][j], ah[i][0],ah[i][1],ah[i][2],ah[i][3], bl[j][0],bl[j][1]);
        MMA_F16(acc[i][j], ah[i][0],ah[i][1],ah[i][2],ah[i][3], bh[j][0],bh[j][1]);
      }
  };

  load(kbeg);
  store(0);
  __syncthreads();
  int buf = 0;
  for (int k0 = kbeg + 16; k0 < kend; k0 += 16) {
    load(k0);
    comp(buf);
    store(buf ^ 1);
    __syncthreads();
    buf ^= 1;
  }
  comp(buf);
}

#define SMEM_F16 \
  __shared__ __align__(16) unsigned Ah[2*1024]; \
  __shared__ __align__(16) unsigned Al[2*1024]; \
  __shared__ __align__(16) unsigned Bh[2*1024]; \
  __shared__ __align__(16) unsigned Bl[2*1024];

// ================= TF32 tile (MoE), BK=8, unchanged from R3 =================
__device__ __forceinline__ unsigned f2tf(float x) {
  unsigned r;
  asm("cvt.rna.tf32.f32 %0, %1;" : "=r"(r) : "f"(x));
  return r;
}

#define MMA_TF32(ACC, A0,A1,A2,A3, B0,B1) \
  asm volatile( \
    "mma.sync.aligned.m16n8k8.row.col.f32.tf32.tf32.f32 " \
    "{%0,%1,%2,%3}, {%4,%5,%6,%7}, {%8,%9}, {%0,%1,%2,%3};" \
    : "+f"((ACC)[0]), "+f"((ACC)[1]), "+f"((ACC)[2]), "+f"((ACC)[3]) \
    : "r"(A0), "r"(A1), "r"(A2), "r"(A3), "r"(B0), "r"(B1))

template<bool BT>
__device__ __forceinline__ void tf32_tile8(
    float (&acc)[4][4][4],
    const float* __restrict__ A, int lda, const int* __restrict__ rowmap, int m0,
    const float* __restrict__ B, int ldb, int n0,
    int kbeg, int kend,
    float* __restrict__ As, float* __restrict__ Bs)
{
  const int tid = threadIdx.x, lane = tid & 31, warp = tid >> 5;
  const int wm = warp & 1, wn = warp >> 1;

  const int am = tid >> 1, akq = (tid & 1) << 2;
  const int ar = rowmap ? rowmap[m0 + am] : (m0 + am);
  const float* aptr = A + (size_t)ar * lda + akq;
  const int asto = (am>>4)*128 + (((am&8)>>3) | ((akq&4)>>1))*32 + (am&7)*4;

  const float* bptr;
  int bn, bkq;
  if (BT) { bn = tid >> 1;  bkq = (tid & 1) << 2; bptr = B + (size_t)(n0 + bn)*ldb + bkq; }
  else    { bn = tid & 127; bkq = (tid >> 7) << 2; bptr = B + n0 + bn; }
  const int bsto = (bn>>3)*64 + ((bkq&4)>>2)*32 + (bn&7)*4;

  int aro[4], bro[4];
#pragma unroll
  for (int i = 0; i < 4; i++) aro[i] = (wm*4 + i)*128 + lane;
#pragma unroll
  for (int j = 0; j < 4; j++) bro[j] = (wn*4 + j)*64 + lane;

  float4 aS, bS;
  auto load = [&](int k0) {
    aS = *(const float4*)(aptr + k0);
    if (BT) {
      bS = *(const float4*)(bptr + k0);
    } else {
      const float* p = bptr + (size_t)(k0 + bkq) * ldb;
      bS.x = p[0]; bS.y = p[ldb]; bS.z = p[2*ldb]; bS.w = p[3*ldb];
    }
  };
  auto store = [&](int buf) {
    uint4 h;
    h.x = f2tf(aS.x); h.y = f2tf(aS.y); h.z = f2tf(aS.z); h.w = f2tf(aS.w);
    *(uint4*)(As + buf*1024 + asto) = h;
    uint4 hb;
    hb.x = f2tf(bS.x); hb.y = f2tf(bS.y); hb.z = f2tf(bS.z); hb.w = f2tf(bS.w);
    *(uint4*)(Bs + buf*1024 + bsto) = hb;
  };
  auto comp = [&](int buf) {
    unsigned ah[4][4], bh[4][2];
#pragma unroll
    for (int i = 0; i < 4; i++)
#pragma unroll
      for (int e = 0; e < 4; e++)
        ah[i][e] = __float_as_uint(As[buf*1024 + aro[i] + e*32]);
#pragma unroll
    for (int j = 0; j < 4; j++)
#pragma unroll
      for (int e = 0; e < 2; e++)
        bh[j][e] = __float_as_uint(Bs[buf*1024 + bro[j] + e*32]);
#pragma unroll
    for (int i = 0; i < 4; i++)
#pragma unroll
      for (int j = 0; j < 4; j++)
        MMA_TF32(acc[i][j], ah[i][0],ah[i][1],ah[i][2],ah[i][3], bh[j][0],bh[j][1]);
  };

  load(kbeg);
  store(0);
  __syncthreads();
  int buf = 0;
  for (int k0 = kbeg + 8; k0 < kend; k0 += 8) {
    load(k0);
    comp(buf);
    store(buf ^ 1);
    __syncthreads();
    buf ^= 1;
  }
  comp(buf);
}

#define SMEM_TF32 \
  __shared__ __align__(16) float As[2*1024];  \
  __shared__ __align__(16) float Bs[2*1024];

#define EPI_SETUP() \
  const int lane = threadIdx.x & 31, warp = threadIdx.x >> 5; \
  const int wm = warp & 1, wn = warp >> 1; \
  const int g = lane >> 2, tg = lane & 3;

// ---------------- LayerNorm ----------------
__device__ __forceinline__ void ln_body(const float* __restrict__ x,
    const float* __restrict__ w, const float* __restrict__ b, float* __restrict__ y)
{
  float s = 0.f, ss = 0.f;
  for (int d = threadIdx.x*4; d < DM; d += 1024) {
    float4 v = *(const float4*)(x + d);
    s  += v.x + v.y + v.z + v.w;
    ss += v.x*v.x + v.y*v.y + v.z*v.z + v.w*v.w;
  }
  __shared__ float shA[8], shB[8];
  const int lane = threadIdx.x & 31, wi = threadIdx.x >> 5;
  for (int o = 16; o; o >>= 1) { s += __shfl_xor_sync(0xffffffffu, s, o); ss += __shfl_xor_sync(0xffffffffu, ss, o); }
  if (lane == 0) { shA[wi] = s; shB[wi] = ss; }
  __syncthreads();
  float st = 0.f, sst = 0.f;
#pragma unroll
  for (int k = 0; k < 8; k++) { st += shA[k]; sst += shB[k]; }
  const float mean = st / (float)DM;
  const float var  = sst / (float)DM - mean*mean;
  const float rstd = rsqrtf(var + 1e-5f);
  for (int d = threadIdx.x*4; d < DM; d += 1024) {
    float4 v = *(const float4*)(x + d);
    float4 wv = *(const float4*)(w + d);
    float4 bv = *(const float4*)(b + d);
    float4 o;
    o.x = (v.x-mean)*rstd*wv.x + bv.x;
    o.y = (v.y-mean)*rstd*wv.y + bv.y;
    o.z = (v.z-mean)*rstd*wv.z + bv.z;
    o.w = (v.w-mean)*rstd*wv.w + bv.w;
    *(float4*)(y + d) = o;
  }
}

__global__ __launch_bounds__(256) void k_ln1(const float* __restrict__ hidden,
    const float* __restrict__ w, const float* __restrict__ b)
{
  const int row = blockIdx.x;
  ln_body(hidden + (size_t)row*DM, w, b, g_xln + (size_t)row*DM);
}

__global__ __launch_bounds__(256) void k_ln2(const float* __restrict__ w, const float* __restrict__ b)
{
  const int row = blockIdx.x;
  ln_body(g_res2 + (size_t)row*DM, w, b, g_xln + (size_t)row*DM);
}

// ---------------- QKV GEMM (fp16-split) ----------------
__global__ __launch_bounds__(256) void t_gemm_qkv(const float* __restrict__ W,
                                                  const float* __restrict__ bias)
{
  SMEM_F16;
  float acc[4][4][4] = {};
  const int m0 = blockIdx.y * 128, n0 = blockIdx.x * 128;
  f16_tile16<false>(acc, g_xln, DM, m0, W, QKVN, n0, 0, DM, Ah, Al, Bh, Bl);
  EPI_SETUP();
#pragma unroll
  for (int i = 0; i < 4; i++)
#pragma unroll
    for (int j = 0; j < 4; j++) {
      const int row = m0 + wm*64 + i*16 + g;
      const int col = n0 + wn*32 + j*8 + tg*2;
      const float b0 = bias[col], b1 = bias[col+1];
      *(float2*)(g_qkv + (size_t)row*QKVN + col)     = make_float2(acc[i][j][0]+b0, acc[i][j][1]+b1);
      *(float2*)(g_qkv + (size_t)(row+8)*QKVN + col) = make_float2(acc[i][j][2]+b0, acc[i][j][3]+b1);
    }
}

// ---------------- RoPE + split ----------------
__global__ __launch_bounds__(256) void k_rope(const float* __restrict__ cosb,
                                              const float* __restrict__ sinb)
{
  const int s = blockIdx.y;
  const int col = blockIdx.x * 256 + threadIdx.x;
  const float* qrow = g_qkv + (size_t)s * QKVN;
  const float x = qrow[col];
  if (col < NH*HD) {
    const int h = col >> 7, d = col & 127;
    const float c = cosb[s*HD+d], sn = sinb[s*HD+d];
    const float p = (d < 64) ? -qrow[col+64] : qrow[col-64];
    g_Q[((size_t)h*SS + s)*HD + d] = x*c + p*sn;
  } else if (col < (NH+NKV)*HD) {
    const int cc = col - NH*HD;
    const int h = cc >> 7, d = cc & 127;
    const float c = cosb[s*HD+d], sn = sinb[s*HD+d];
    const float p = (d < 64) ? -qrow[col+64] : qrow[col-64];
    g_K[((size_t)h*SS + s)*HD + d] = x*c + p*sn;
  } else {
    const int cc = col - (NH+NKV)*HD;
    const int h = cc >> 7, d = cc & 127;
    g_V[((size_t)h*SS + s)*HD + d] = x;
  }
}

// ---------------- scores (fp16-split) ----------------
__global__ __launch_bounds__(256) void t_scores(float scale)
{
  if (blockIdx.x > blockIdx.y) return;
  const int h = blockIdx.z;
  SMEM_F16;
  float acc[4][4][4] = {};
  const int m0 = blockIdx.y * 128, n0 = blockIdx.x * 128;
  f16_tile16<true>(acc, g_Q + (size_t)h*SS*HD, HD, m0,
                   g_K + (size_t)(h>>2)*SS*HD, HD, n0, 0, HD, Ah, Al, Bh, Bl);
  EPI_SETUP();
  float* Ph = g_P + (size_t)h*SS*SS;
#pragma unroll
  for (int i = 0; i < 4; i++)
#pragma unroll
    for (int j = 0; j < 4; j++) {
      const int row = m0 + wm*64 + i*16 + g;
      const int col = n0 + wn*32 + j*8 + tg*2;
      *(float2*)(Ph + (size_t)row*SS + col)     = make_float2(acc[i][j][0]*scale, acc[i][j][1]*scale);
      *(float2*)(Ph + (size_t)(row+8)*SS + col) = make_float2(acc[i][j][2]*scale, acc[i][j][3]*scale);
    }
}

// ---------------- softmax ----------------
__global__ __launch_bounds__(256) void k_softmax()
{
  const int i = blockIdx.x, h = blockIdx.y;
  float* row = g_P + ((size_t)h*SS + i)*SS;
  const int jm = i;
  const int jend = ((i >> 7) + 1) << 7;
  __shared__ float buf[2048];
  __shared__ float redA[8], redB[8];
  const int tid = threadIdx.x;
  float mx = -1e30f;
  for (int j = tid; j <= jm; j += 256) { float v = row[j]; buf[j] = v; mx = fmaxf(mx, v); }
  for (int o = 16; o; o >>= 1) mx = fmaxf(mx, __shfl_xor_sync(0xffffffffu, mx, o));
  if ((tid & 31) == 0) redA[tid >> 5] = mx;
  __syncthreads();
  float m = redA[0];
#pragma unroll
  for (int k = 1; k < 8; k++) m = fmaxf(m, redA[k]);
  float s = 0.f;
  for (int j = tid; j <= jm; j += 256) { float e = expf(buf[j] - m); buf[j] = e; s += e; }
  for (int o = 16; o; o >>= 1) s += __shfl_xor_sync(0xffffffffu, s, o);
  if ((tid & 31) == 0) redB[tid >> 5] = s;
  __syncthreads();
  float st = 0.f;
#pragma unroll
  for (int k = 0; k < 8; k++) st += redB[k];
  const float inv = 1.f / st;
  for (int j = tid; j < jend; j += 256) row[j] = (j <= jm) ? buf[j]*inv : 0.f;
}

// ---------------- PV (fp16-split) ----------------
__global__ __launch_bounds__(256) void t_pv()
{
  const int h = blockIdx.z, bm = blockIdx.y;
  SMEM_F16;
  float acc[4][4][4] = {};
  const int m0 = bm * 128;
  const int kend = (bm + 1) * 128;
  f16_tile16<false>(acc, g_P + (size_t)h*SS*SS, SS, m0,
                    g_V + (size_t)(h>>2)*SS*HD, HD, 0, 0, kend, Ah, Al, Bh, Bl);
  EPI_SETUP();
#pragma unroll
  for (int i = 0; i < 4; i++)
#pragma unroll
    for (int j = 0; j < 4; j++) {
      const int row = m0 + wm*64 + i*16 + g;
      const int col = wn*32 + j*8 + tg*2;
      *(float2*)(g_oc + (size_t)row*DM + h*HD + col)     = make_float2(acc[i][j][0], acc[i][j][1]);
      *(float2*)(g_oc + (size_t)(row+8)*DM + h*HD + col) = make_float2(acc[i][j][2], acc[i][j][3]);
    }
}

// ---------------- O proj + residual (fp16-split) ----------------
__global__ __launch_bounds__(256) void t_oproj(const float* __restrict__ W,
    const float* __restrict__ bias, const float* __restrict__ resid)
{
  SMEM_F16;
  float acc[4][4][4] = {};
  const int m0 = blockIdx.y * 128, n0 = blockIdx.x * 128;
  f16_tile16<false>(acc, g_oc, DM, m0, W, DM, n0, 0, DM, Ah, Al, Bh, Bl);
  EPI_SETUP();
#pragma unroll
  for (int i = 0; i < 4; i++)
#pragma unroll
    for (int j = 0; j < 4; j++) {
      const int row = m0 + wm*64 + i*16 + g;
      const int col = n0 + wn*32 + j*8 + tg*2;
      const float b0 = bias[col], b1 = bias[col+1];
      float2 r0 = *(const float2*)(resid + (size_t)row*DM + col);
      float2 r1 = *(const float2*)(resid + (size_t)(row+8)*DM + col);
      *(float2*)(g_res2 + (size_t)row*DM + col)     = make_float2(acc[i][j][0]+b0+r0.x, acc[i][j][1]+b1+r0.y);
      *(float2*)(g_res2 + (size_t)(row+8)*DM + col) = make_float2(acc[i][j][2]+b0+r1.x, acc[i][j][3]+b1+r1.y);
    }
}

__global__ __launch_bounds__(256) void k_copyres(float* __restrict__ dst)
{
  const int i = blockIdx.x * 256 + threadIdx.x;
  ((float4*)dst)[i] = ((const float4*)g_res2)[i];
}

// ---------------- router + sparsemixer ----------------
__global__ void k_zero() { if (threadIdx.x < NE) g_cnt[threadIdx.x] = 0; }

__global__ __launch_bounds__(256) void k_router(const float* __restrict__ gw)
{
  const int t = blockIdx.x;
  const float* x = g_xln + (size_t)t * DM;
  float acc[NE];
#pragma unroll
  for (int e = 0; e < NE; e++) acc[e] = 0.f;
  for (int d = threadIdx.x; d < DM; d += 256) {
    const float xv = x[d];
    const float* gr = gw + d * NE;
#pragma unroll
    for (int e = 0; e < NE; e++) acc[e] += xv * gr[e];
  }
  __shared__ float sh[NE][8];
  const int lane = threadIdx.x & 31, w = threadIdx.x >> 5;
#pragma unroll
  for (int e = 0; e < NE; e++) {
    float v = acc[e];
    for (int o = 16; o; o >>= 1) v += __shfl_xor_sync(0xffffffffu, v, o);
    if (lane == 0) sh[e][w] = v;
  }
  __syncthreads();
  if (threadIdx.x == 0) {
    float s[NE];
#pragma unroll
    for (int e = 0; e < NE; e++) {
      float v = 0.f;
#pragma unroll
      for (int k = 0; k < 8; k++) v += sh[e][k];
      s[e] = v;
    }
    const float teps = 0.02f;
    int i1 = 0;
    for (int e = 1; e < NE; e++) if (s[e] > s[i1]) i1 = e;
    const float mx1 = s[i1];
    float den = 0.f;
    for (int e = 0; e < NE; e++) {
      const float f = fmaxf(fabsf(s[e]), mx1);
      if (!((mx1 - s[e]) / f > teps)) den += expf(s[e] - mx1);
    }
    const float w1 = 1.f / den;
    int i2 = -1; float mx2 = -INFINITY;
    for (int e = 0; e < NE; e++) if (e != i1 && s[e] > mx2) { mx2 = s[e]; i2 = e; }
    float den2 = 0.f;
    for (int e = 0; e < NE; e++) {
      if (e == i1) continue;
      const float f = fmaxf(fabsf(s[e]), mx2);
      if (!((mx2 - s[e]) / f > teps)) den2 += expf(s[e] - mx2);
    }
    const float w2 = 1.f / den2;
    g_topw[t*2] = w1; g_topw[t*2+1] = w2;
    g_topid[t*2] = i1; g_topid[t*2+1] = i2;
    atomicAdd(&g_cnt[i1], 1); atomicAdd(&g_cnt[i2], 1);
  }
}

__global__ __launch_bounds__(256) void k_setup()
{
  const int tid = threadIdx.x;
  if (tid == 0) {
    for (int t = 0; t < MAXTILES; t++) g_tileexp[t] = -1;
    int o = 0;
    for (int e = 0; e < NE; e++) {
      g_off[e] = o;
      const int tiles = (g_cnt[e] + 127) >> 7;
      for (int t = 0; t < tiles; t++) g_tileexp[(o >> 7) + t] = e;
      o += tiles << 7;
    }
  }
  for (int i = tid; i < MAXROWS; i += 256) { g_rows[i] = 0; g_wv[i] = 0.f; }
  if (tid < NE) g_cnt2[tid] = 0;
}

__global__ __launch_bounds__(256) void k_scatter()
{
  const int t = blockIdx.x * 256 + threadIdx.x;
  if (t >= SS) return;
#pragma unroll
  for (int j = 0; j < 2; j++) {
    const int e = g_topid[t*2+j];
    const int pos = g_off[e] + atomicAdd(&g_cnt2[e], 1);
    g_rows[pos] = t;
    g_wv[pos] = g_topw[t*2+j];
    g_slot[t*2+j] = pos;
  }
}

// ---------------- MoE GEMMs (1xTF32) ----------------
template<int EPI>
__global__ __launch_bounds__(256) void t_moe_gu(const float* __restrict__ Wall)
{
  const int e = g_tileexp[blockIdx.y];
  if (e < 0) return;
  SMEM_TF32;
  float acc[4][4][4] = {};
  const int m0 = blockIdx.y * 128, n0 = blockIdx.x * 128;
  const float* B = Wall + (size_t)e * FF * DM;
  tf32_tile8<true>(acc, g_xln, DM, g_rows, m0, B, DM, n0, 0, DM, As, Bs);
  EPI_SETUP();
#pragma unroll
  for (int i = 0; i < 4; i++)
#pragma unroll
    for (int j = 0; j < 4; j++) {
      const int row = m0 + wm*64 + i*16 + g;
      const int col = n0 + wn*32 + j*8 + tg*2;
      float* p0 = g_gbuf + (size_t)row*FF + col;
      float* p1 = g_gbuf + (size_t)(row+8)*FF + col;
      if (EPI == 0) {
        *(float2*)p0 = make_float2(acc[i][j][0], acc[i][j][1]);
        *(float2*)p1 = make_float2(acc[i][j][2], acc[i][j][3]);
      } else {
        float2 g0 = *(float2*)p0;
        float2 g1 = *(float2*)p1;
        float2 v0, v1;
        v0.x = (g0.x/(1.f+expf(-g0.x))) * acc[i][j][0];
        v0.y = (g0.y/(1.f+expf(-g0.y))) * acc[i][j][1];
        v1.x = (g1.x/(1.f+expf(-g1.x))) * acc[i][j][2];
        v1.y = (g1.y/(1.f+expf(-g1.y))) * acc[i][j][3];
        *(float2*)p0 = v0;
        *(float2*)p1 = v1;
      }
    }
}

__global__ __launch_bounds__(256) void t_moe_down(const float* __restrict__ Wall)
{
  const int e = g_tileexp[blockIdx.y];
  if (e < 0) return;
  SMEM_TF32;
  float acc[4][4][4] = {};
  const int m0 = blockIdx.y * 128, n0 = blockIdx.x * 128;
  const float* B = Wall + (size_t)e * DM * FF;
  tf32_tile8<true>(acc, g_gbuf, FF, nullptr, m0, B, FF, n0, 0, FF, As, Bs);
  EPI_SETUP();
#pragma unroll
  for (int i = 0; i < 4; i++)
#pragma unroll
    for (int j = 0; j < 4; j++) {
      const int row = m0 + wm*64 + i*16 + g;
      const int col = n0 + wn*32 + j*8 + tg*2;
      const float w0 = g_wv[row], w1 = g_wv[row+8];
      *(float2*)(g_dout + (size_t)row*DM + col)     = make_float2(acc[i][j][0]*w0, acc[i][j][1]*w0);
      *(float2*)(g_dout + (size_t)(row+8)*DM + col) = make_float2(acc[i][j][2]*w1, acc[i][j][3]*w1);
    }
}

__global__ __launch_bounds__(256) void k_combine(float* __restrict__ out)
{
  const int t = blockIdx.y;
  const int d = blockIdx.x * 256 + threadIdx.x;
  const int s0 = g_slot[t*2], s1 = g_slot[t*2+1];
  out[(size_t)t*DM + d] = g_dout[(size_t)s0*DM + d] + g_dout[(size_t)s1*DM + d];
}

// ---------------- launch ----------------
extern "C" void kernel_launch(void* const* d_in, const int* in_sizes, int n_in,
                              void* d_out, int out_size)
{
  const float* hidden = (const float*)d_in[0];
  const float* cosb   = (const float*)d_in[1];
  const float* sinb   = (const float*)d_in[2];
  const float* ln1w   = (const float*)d_in[3];
  const float* ln1b   = (const float*)d_in[4];
  const float* ln2w   = (const float*)d_in[5];
  const float* ln2b   = (const float*)d_in[6];
  const float* wqkv   = (const float*)d_in[7];
  const float* bqkv   = (const float*)d_in[8];
  const float* wo     = (const float*)d_in[9];
  const float* bo     = (const float*)d_in[10];
  const float* gatew  = (const float*)d_in[11];
  const float* wgate  = (const float*)d_in[12];
  const float* wup    = (const float*)d_in[13];
  const float* wdown  = (const float*)d_in[14];
  float* out = (float*)d_out;

  k_zero<<<1, 32>>>();
  k_ln1<<<SS, 256>>>(hidden, ln1w, ln1b);
  t_gemm_qkv<<<dim3(QKVN/128, SS/128), 256>>>(wqkv, bqkv);
  k_rope<<<dim3(QKVN/256, SS), 256>>>(cosb, sinb);
  t_scores<<<dim3(SS/128, SS/128, NH), 256>>>(0.08838834764831845f);
  k_softmax<<<dim3(SS, NH), 256>>>();
  t_pv<<<dim3(1, SS/128, NH), 256>>>();
  t_oproj<<<dim3(DM/128, SS/128), 256>>>(wo, bo, hidden);
  if (out_size >= 2 * SS * DM)
    k_copyres<<<(SS*DM/4)/256, 256>>>(out + (size_t)SS*DM);
  k_ln2<<<SS, 256>>>(ln2w, ln2b);
  k_router<<<SS, 256>>>(gatew);
  k_setup<<<1, 256>>>();
  k_scatter<<<(SS + 255)/256, 256>>>();
  t_moe_gu<0><<<dim3(FF/128, MAXTILES), 256>>>(wgate);
  t_moe_gu<1><<<dim3(FF/128, MAXTILES), 256>>>(wup);
  t_moe_down<<<dim3(DM/128, MAXTILES), 256>>>(wdown);
  k_combine<<<dim3(DM/256, SS), 256>>>(out);
}

// round 7
// speedup vs baseline: 3.5798x; 1.3889x over previous
#include <cuda_runtime.h>
#include <cuda_fp16.h>
#include <math.h>

#define SS   2048
#define DM   2048
#define NH   16
#define NKV  4
#define HD   128
#define NE   8
#define FF   4096
#define QKVN 3072
#define MAXROWS 5120
#define MAXTILES 40

// ---------------- scratch ----------------
__device__ float g_xln[SS*DM];
__device__ float g_qkv[SS*QKVN];
__device__ float g_Q[NH*SS*HD];
__device__ float g_K[NKV*SS*HD];
__device__ float g_V[NKV*SS*HD];
__device__ float g_P[67108864];
__device__ float g_oc[SS*DM];
__device__ float g_res2[SS*DM];
__device__ float g_gbuf[MAXROWS*FF];
__device__ float g_dout[MAXROWS*DM];
__device__ float g_topw[SS*2];
__device__ int   g_topid[SS*2];
__device__ int   g_cnt[NE];
__device__ int   g_cnt2[NE];
__device__ int   g_off[NE];
__device__ int   g_rows[MAXROWS];
__device__ float g_wv[MAXROWS];
__device__ int   g_slot[SS*2];
__device__ int   g_tileexp[MAXTILES];

// ================= fp16 MMA tile, BK=16 =================
// CTA 128x128, 256 threads = 8 warps (2 M x 4 N), warp tile 64x32,
// m16n8k16 fp16 mma, fp32 accum.
// SPLIT=3: hi/lo two-term split (lo*hi + hi*lo + hi*hi) -> ~fp32 precision.
// SPLIT=1: plain fp16 (same mantissa as TF32, 2x throughput).
// Fragment-order smem (packed half2 words, u32):
//   A word [mt(8)][e(4)][lane(32)] : e = ((k&8)>>2)|((m&8)>>3),
//                                    lane = (m&7)*4 + ((k&7)>>1)
//   B word [nt(16)][e(2)][lane(32)]: e = (k&8)>>3, lane = (n&7)*4 + ((k&7)>>1)

#define MMA_F16(ACC, A0,A1,A2,A3, B0,B1) \
  asm volatile("mma.sync.aligned.m16n8k16.row.col.f32.f16.f16.f32 " \
    "{%0,%1,%2,%3}, {%4,%5,%6,%7}, {%8,%9}, {%0,%1,%2,%3};" \
    : "+f"((ACC)[0]),"+f"((ACC)[1]),"+f"((ACC)[2]),"+f"((ACC)[3]) \
    : "r"(A0),"r"(A1),"r"(A2),"r"(A3),"r"(B0),"r"(B1))

__device__ __forceinline__ void cvt2(float x, float y, unsigned &h, unsigned &l) {
  __half hx = __float2half_rn(x), hy = __float2half_rn(y);
  __half lx = __float2half_rn(x - __half2float(hx));
  __half ly = __float2half_rn(y - __half2float(hy));
  h = (unsigned)__half_as_ushort(hx) | ((unsigned)__half_as_ushort(hy) << 16);
  l = (unsigned)__half_as_ushort(lx) | ((unsigned)__half_as_ushort(ly) << 16);
}
__device__ __forceinline__ unsigned cvt2h(float x, float y) {
  __half hx = __float2half_rn(x), hy = __float2half_rn(y);
  return (unsigned)__half_as_ushort(hx) | ((unsigned)__half_as_ushort(hy) << 16);
}

template<bool BT, int SPLIT>
__device__ __forceinline__ void f16_tile16(
    float (&acc)[4][4][4],
    const float* __restrict__ A, int lda, const int* __restrict__ rowmap, int m0,
    const float* __restrict__ B, int ldb, int n0,
    int kbeg, int kend,
    unsigned* __restrict__ Ah, unsigned* __restrict__ Al,
    unsigned* __restrict__ Bh, unsigned* __restrict__ Bl)
{
  const int tid = threadIdx.x, lane = tid & 31, warp = tid >> 5;
  const int wm = warp & 1, wn = warp >> 1;

  const float* aptr[2]; int aidx[2];
#pragma unroll
  for (int it = 0; it < 2; it++) {
    int q = tid + it*256;
    int m = q >> 2, kq = (q & 3) << 2;
    int r = rowmap ? rowmap[m0 + m] : (m0 + m);
    aptr[it] = A + (size_t)r * lda + kq;
    aidx[it] = (m>>4)*128 + (((kq&8)>>2) | ((m&8)>>3))*32 + (m&7)*4 + ((kq&4)>>1);
  }
  const float* bptr[2]; int bidx[2]; int bkq[2];
#pragma unroll
  for (int it = 0; it < 2; it++) {
    int q = tid + it*256;
    int n, kq;
    if (BT) { n = q >> 2;  kq = (q & 3) << 2; }
    else    { n = q & 127; kq = (q >> 7) << 2; }
    bkq[it] = kq;
    bptr[it] = BT ? (B + (size_t)(n0 + n) * ldb + kq) : (B + n0 + n);
    bidx[it] = (n>>3)*64 + ((kq&8)>>3)*32 + (n&7)*4 + ((kq&4)>>1);
  }

  float4 av[2], bv[2];
  auto load = [&](int k0) {
#pragma unroll
    for (int it = 0; it < 2; it++) {
      av[it] = *(const float4*)(aptr[it] + k0);
      if (BT) {
        bv[it] = *(const float4*)(bptr[it] + k0);
      } else {
        const float* p = bptr[it] + (size_t)(k0 + bkq[it]) * ldb;
        bv[it].x = p[0]; bv[it].y = p[ldb]; bv[it].z = p[2*ldb]; bv[it].w = p[3*ldb];
      }
    }
  };
  auto store = [&](int buf) {
#pragma unroll
    for (int it = 0; it < 2; it++) {
      if (SPLIT == 3) {
        unsigned h0,l0,h1,l1;
        cvt2(av[it].x, av[it].y, h0, l0);
        cvt2(av[it].z, av[it].w, h1, l1);
        *(uint2*)(Ah + buf*1024 + aidx[it]) = make_uint2(h0, h1);
        *(uint2*)(Al + buf*1024 + aidx[it]) = make_uint2(l0, l1);
        cvt2(bv[it].x, bv[it].y, h0, l0);
        cvt2(bv[it].z, bv[it].w, h1, l1);
        *(uint2*)(Bh + buf*1024 + bidx[it]) = make_uint2(h0, h1);
        *(uint2*)(Bl + buf*1024 + bidx[it]) = make_uint2(l0, l1);
      } else {
        *(uint2*)(Ah + buf*1024 + aidx[it]) =
          make_uint2(cvt2h(av[it].x, av[it].y), cvt2h(av[it].z, av[it].w));
        *(uint2*)(Bh + buf*1024 + bidx[it]) =
          make_uint2(cvt2h(bv[it].x, bv[it].y), cvt2h(bv[it].z, bv[it].w));
      }
    }
  };
  auto comp = [&](int buf) {
    unsigned ah[4][4], al[4][4], bh[4][2], bl[4][2];
#pragma unroll
    for (int i = 0; i < 4; i++)
#pragma unroll
      for (int e = 0; e < 4; e++) {
        int off = buf*1024 + (wm*4 + i)*128 + e*32 + lane;
        ah[i][e] = Ah[off];
        if (SPLIT == 3) al[i][e] = Al[off];
      }
#pragma unroll
    for (int j = 0; j < 4; j++)
#pragma unroll
      for (int e = 0; e < 2; e++) {
        int off = buf*1024 + (wn*4 + j)*64 + e*32 + lane;
        bh[j][e] = Bh[off];
        if (SPLIT == 3) bl[j][e] = Bl[off];
      }
#pragma unroll
    for (int i = 0; i < 4; i++)
#pragma unroll
      for (int j = 0; j < 4; j++) {
        if (SPLIT == 3) {
          MMA_F16(acc[i][j], al[i][0],al[i][1],al[i][2],al[i][3], bh[j][0],bh[j][1]);
          MMA_F16(acc[i][j], ah[i][0],ah[i][1],ah[i][2],ah[i][3], bl[j][0],bl[j][1]);
        }
        MMA_F16(acc[i][j], ah[i][0],ah[i][1],ah[i][2],ah[i][3], bh[j][0],bh[j][1]);
      }
  };

  load(kbeg);
  store(0);
  __syncthreads();
  int buf = 0;
  for (int k0 = kbeg + 16; k0 < kend; k0 += 16) {
    load(k0);
    comp(buf);
    store(buf ^ 1);
    __syncthreads();
    buf ^= 1;
  }
  comp(buf);
}

#define SMEM_F16S3 \
  __shared__ __align__(16) unsigned Ah[2*1024]; \
  __shared__ __align__(16) unsigned Al[2*1024]; \
  __shared__ __align__(16) unsigned Bh[2*1024]; \
  __shared__ __align__(16) unsigned Bl[2*1024];

#define SMEM_F16S1 \
  __shared__ __align__(16) unsigned Ah[2*1024]; \
  __shared__ __align__(16) unsigned Bh[2*1024];

#define EPI_SETUP() \
  const int lane = threadIdx.x & 31, warp = threadIdx.x >> 5; \
  const int wm = warp & 1, wn = warp >> 1; \
  const int g = lane >> 2, tg = lane & 3;

// ---------------- LayerNorm ----------------
__device__ __forceinline__ void ln_body(const float* __restrict__ x,
    const float* __restrict__ w, const float* __restrict__ b, float* __restrict__ y)
{
  float s = 0.f, ss = 0.f;
  for (int d = threadIdx.x*4; d < DM; d += 1024) {
    float4 v = *(const float4*)(x + d);
    s  += v.x + v.y + v.z + v.w;
    ss += v.x*v.x + v.y*v.y + v.z*v.z + v.w*v.w;
  }
  __shared__ float shA[8], shB[8];
  const int lane = threadIdx.x & 31, wi = threadIdx.x >> 5;
  for (int o = 16; o; o >>= 1) { s += __shfl_xor_sync(0xffffffffu, s, o); ss += __shfl_xor_sync(0xffffffffu, ss, o); }
  if (lane == 0) { shA[wi] = s; shB[wi] = ss; }
  __syncthreads();
  float st = 0.f, sst = 0.f;
#pragma unroll
  for (int k = 0; k < 8; k++) { st += shA[k]; sst += shB[k]; }
  const float mean = st / (float)DM;
  const float var  = sst / (float)DM - mean*mean;
  const float rstd = rsqrtf(var + 1e-5f);
  for (int d = threadIdx.x*4; d < DM; d += 1024) {
    float4 v = *(const float4*)(x + d);
    float4 wv = *(const float4*)(w + d);
    float4 bv = *(const float4*)(b + d);
    float4 o;
    o.x = (v.x-mean)*rstd*wv.x + bv.x;
    o.y = (v.y-mean)*rstd*wv.y + bv.y;
    o.z = (v.z-mean)*rstd*wv.z + bv.z;
    o.w = (v.w-mean)*rstd*wv.w + bv.w;
    *(float4*)(y + d) = o;
  }
}

__global__ __launch_bounds__(256) void k_ln1(const float* __restrict__ hidden,
    const float* __restrict__ w, const float* __restrict__ b)
{
  const int row = blockIdx.x;
  ln_body(hidden + (size_t)row*DM, w, b, g_xln + (size_t)row*DM);
}

__global__ __launch_bounds__(256) void k_ln2(const float* __restrict__ w, const float* __restrict__ b)
{
  const int row = blockIdx.x;
  ln_body(g_res2 + (size_t)row*DM, w, b, g_xln + (size_t)row*DM);
}

// ---------------- QKV GEMM (fp16-split) ----------------
__global__ __launch_bounds__(256) void t_gemm_qkv(const float* __restrict__ W,
                                                  const float* __restrict__ bias)
{
  SMEM_F16S3;
  float acc[4][4][4] = {};
  const int m0 = blockIdx.y * 128, n0 = blockIdx.x * 128;
  f16_tile16<false,3>(acc, g_xln, DM, nullptr, m0, W, QKVN, n0, 0, DM, Ah, Al, Bh, Bl);
  EPI_SETUP();
#pragma unroll
  for (int i = 0; i < 4; i++)
#pragma unroll
    for (int j = 0; j < 4; j++) {
      const int row = m0 + wm*64 + i*16 + g;
      const int col = n0 + wn*32 + j*8 + tg*2;
      const float b0 = bias[col], b1 = bias[col+1];
      *(float2*)(g_qkv + (size_t)row*QKVN + col)     = make_float2(acc[i][j][0]+b0, acc[i][j][1]+b1);
      *(float2*)(g_qkv + (size_t)(row+8)*QKVN + col) = make_float2(acc[i][j][2]+b0, acc[i][j][3]+b1);
    }
}

// ---------------- RoPE + split ----------------
__global__ __launch_bounds__(256) void k_rope(const float* __restrict__ cosb,
                                              const float* __restrict__ sinb)
{
  const int s = blockIdx.y;
  const int col = blockIdx.x * 256 + threadIdx.x;
  const float* qrow = g_qkv + (size_t)s * QKVN;
  const float x = qrow[col];
  if (col < NH*HD) {
    const int h = col >> 7, d = col & 127;
    const float c = cosb[s*HD+d], sn = sinb[s*HD+d];
    const float p = (d < 64) ? -qrow[col+64] : qrow[col-64];
    g_Q[((size_t)h*SS + s)*HD + d] = x*c + p*sn;
  } else if (col < (NH+NKV)*HD) {
    const int cc = col - NH*HD;
    const int h = cc >> 7, d = cc & 127;
    const float c = cosb[s*HD+d], sn = sinb[s*HD+d];
    const float p = (d < 64) ? -qrow[col+64] : qrow[col-64];
    g_K[((size_t)h*SS + s)*HD + d] = x*c + p*sn;
  } else {
    const int cc = col - (NH+NKV)*HD;
    const int h = cc >> 7, d = cc & 127;
    g_V[((size_t)h*SS + s)*HD + d] = x;
  }
}

// ---------------- scores (fp16-split) ----------------
__global__ __launch_bounds__(256) void t_scores(float scale)
{
  if (blockIdx.x > blockIdx.y) return;
  const int h = blockIdx.z;
  SMEM_F16S3;
  float acc[4][4][4] = {};
  const int m0 = blockIdx.y * 128, n0 = blockIdx.x * 128;
  f16_tile16<true,3>(acc, g_Q + (size_t)h*SS*HD, HD, nullptr, m0,
                     g_K + (size_t)(h>>2)*SS*HD, HD, n0, 0, HD, Ah, Al, Bh, Bl);
  EPI_SETUP();
  float* Ph = g_P + (size_t)h*SS*SS;
#pragma unroll
  for (int i = 0; i < 4; i++)
#pragma unroll
    for (int j = 0; j < 4; j++) {
      const int row = m0 + wm*64 + i*16 + g;
      const int col = n0 + wn*32 + j*8 + tg*2;
      *(float2*)(Ph + (size_t)row*SS + col)     = make_float2(acc[i][j][0]*scale, acc[i][j][1]*scale);
      *(float2*)(Ph + (size_t)(row+8)*SS + col) = make_float2(acc[i][j][2]*scale, acc[i][j][3]*scale);
    }
}

// ---------------- softmax ----------------
__global__ __launch_bounds__(256) void k_softmax()
{
  const int i = blockIdx.x, h = blockIdx.y;
  float* row = g_P + ((size_t)h*SS + i)*SS;
  const int jm = i;
  const int jend = ((i >> 7) + 1) << 7;
  __shared__ float buf[2048];
  __shared__ float redA[8], redB[8];
  const int tid = threadIdx.x;
  float mx = -1e30f;
  for (int j = tid; j <= jm; j += 256) { float v = row[j]; buf[j] = v; mx = fmaxf(mx, v); }
  for (int o = 16; o; o >>= 1) mx = fmaxf(mx, __shfl_xor_sync(0xffffffffu, mx, o));
  if ((tid & 31) == 0) redA[tid >> 5] = mx;
  __syncthreads();
  float m = redA[0];
#pragma unroll
  for (int k = 1; k < 8; k++) m = fmaxf(m, redA[k]);
  float s = 0.f;
  for (int j = tid; j <= jm; j += 256) { float e = expf(buf[j] - m); buf[j] = e; s += e; }
  for (int o = 16; o; o >>= 1) s += __shfl_xor_sync(0xffffffffu, s, o);
  if ((tid & 31) == 0) redB[tid >> 5] = s;
  __syncthreads();
  float st = 0.f;
#pragma unroll
  for (int k = 0; k < 8; k++) st += redB[k];
  const float inv = 1.f / st;
  for (int j = tid; j < jend; j += 256) row[j] = (j <= jm) ? buf[j]*inv : 0.f;
}

// ---------------- PV (fp16-split) ----------------
__global__ __launch_bounds__(256) void t_pv()
{
  const int h = blockIdx.z, bm = blockIdx.y;
  SMEM_F16S3;
  float acc[4][4][4] = {};
  const int m0 = bm * 128;
  const int kend = (bm + 1) * 128;
  f16_tile16<false,3>(acc, g_P + (size_t)h*SS*SS, SS, nullptr, m0,
                      g_V + (size_t)(h>>2)*SS*HD, HD, 0, 0, kend, Ah, Al, Bh, Bl);
  EPI_SETUP();
#pragma unroll
  for (int i = 0; i < 4; i++)
#pragma unroll
    for (int j = 0; j < 4; j++) {
      const int row = m0 + wm*64 + i*16 + g;
      const int col = wn*32 + j*8 + tg*2;
      *(float2*)(g_oc + (size_t)row*DM + h*HD + col)     = make_float2(acc[i][j][0], acc[i][j][1]);
      *(float2*)(g_oc + (size_t)(row+8)*DM + h*HD + col) = make_float2(acc[i][j][2], acc[i][j][3]);
    }
}

// ---------------- O proj + residual (fp16-split) ----------------
__global__ __launch_bounds__(256) void t_oproj(const float* __restrict__ W,
    const float* __restrict__ bias, const float* __restrict__ resid)
{
  SMEM_F16S3;
  float acc[4][4][4] = {};
  const int m0 = blockIdx.y * 128, n0 = blockIdx.x * 128;
  f16_tile16<false,3>(acc, g_oc, DM, nullptr, m0, W, DM, n0, 0, DM, Ah, Al, Bh, Bl);
  EPI_SETUP();
#pragma unroll
  for (int i = 0; i < 4; i++)
#pragma unroll
    for (int j = 0; j < 4; j++) {
      const int row = m0 + wm*64 + i*16 + g;
      const int col = n0 + wn*32 + j*8 + tg*2;
      const float b0 = bias[col], b1 = bias[col+1];
      float2 r0 = *(const float2*)(resid + (size_t)row*DM + col);
      float2 r1 = *(const float2*)(resid + (size_t)(row+8)*DM + col);
      *(float2*)(g_res2 + (size_t)row*DM + col)     = make_float2(acc[i][j][0]+b0+r0.x, acc[i][j][1]+b1+r0.y);
      *(float2*)(g_res2 + (size_t)(row+8)*DM + col) = make_float2(acc[i][j][2]+b0+r1.x, acc[i][j][3]+b1+r1.y);
    }
}

__global__ __launch_bounds__(256) void k_copyres(float* __restrict__ dst)
{
  const int i = blockIdx.x * 256 + threadIdx.x;
  ((float4*)dst)[i] = ((const float4*)g_res2)[i];
}

// ---------------- router + sparsemixer ----------------
__global__ void k_zero() { if (threadIdx.x < NE) g_cnt[threadIdx.x] = 0; }

__global__ __launch_bounds__(256) void k_router(const float* __restrict__ gw)
{
  const int t = blockIdx.x;
  const float* x = g_xln + (size_t)t * DM;
  float acc[NE];
#pragma unroll
  for (int e = 0; e < NE; e++) acc[e] = 0.f;
  for (int d = threadIdx.x; d < DM; d += 256) {
    const float xv = x[d];
    const float* gr = gw + d * NE;
#pragma unroll
    for (int e = 0; e < NE; e++) acc[e] += xv * gr[e];
  }
  __shared__ float sh[NE][8];
  const int lane = threadIdx.x & 31, w = threadIdx.x >> 5;
#pragma unroll
  for (int e = 0; e < NE; e++) {
    float v = acc[e];
    for (int o = 16; o; o >>= 1) v += __shfl_xor_sync(0xffffffffu, v, o);
    if (lane == 0) sh[e][w] = v;
  }
  __syncthreads();
  if (threadIdx.x == 0) {
    float s[NE];
#pragma unroll
    for (int e = 0; e < NE; e++) {
      float v = 0.f;
#pragma unroll
      for (int k = 0; k < 8; k++) v += sh[e][k];
      s[e] = v;
    }
    const float teps = 0.02f;
    int i1 = 0;
    for (int e = 1; e < NE; e++) if (s[e] > s[i1]) i1 = e;
    const float mx1 = s[i1];
    float den = 0.f;
    for (int e = 0; e < NE; e++) {
      const float f = fmaxf(fabsf(s[e]), mx1);
      if (!((mx1 - s[e]) / f > teps)) den += expf(s[e] - mx1);
    }
    const float w1 = 1.f / den;
    int i2 = -1; float mx2 = -INFINITY;
    for (int e = 0; e < NE; e++) if (e != i1 && s[e] > mx2) { mx2 = s[e]; i2 = e; }
    float den2 = 0.f;
    for (int e = 0; e < NE; e++) {
      if (e == i1) continue;
      const float f = fmaxf(fabsf(s[e]), mx2);
      if (!((mx2 - s[e]) / f > teps)) den2 += expf(s[e] - mx2);
    }
    const float w2 = 1.f / den2;
    g_topw[t*2] = w1; g_topw[t*2+1] = w2;
    g_topid[t*2] = i1; g_topid[t*2+1] = i2;
    atomicAdd(&g_cnt[i1], 1); atomicAdd(&g_cnt[i2], 1);
  }
}

__global__ __launch_bounds__(256) void k_setup()
{
  const int tid = threadIdx.x;
  if (tid == 0) {
    for (int t = 0; t < MAXTILES; t++) g_tileexp[t] = -1;
    int o = 0;
    for (int e = 0; e < NE; e++) {
      g_off[e] = o;
      const int tiles = (g_cnt[e] + 127) >> 7;
      for (int t = 0; t < tiles; t++) g_tileexp[(o >> 7) + t] = e;
      o += tiles << 7;
    }
  }
  for (int i = tid; i < MAXROWS; i += 256) { g_rows[i] = 0; g_wv[i] = 0.f; }
  if (tid < NE) g_cnt2[tid] = 0;
}

__global__ __launch_bounds__(256) void k_scatter()
{
  const int t = blockIdx.x * 256 + threadIdx.x;
  if (t >= SS) return;
#pragma unroll
  for (int j = 0; j < 2; j++) {
    const int e = g_topid[t*2+j];
    const int pos = g_off[e] + atomicAdd(&g_cnt2[e], 1);
    g_rows[pos] = t;
    g_wv[pos] = g_topw[t*2+j];
    g_slot[t*2+j] = pos;
  }
}

// ---------------- MoE GEMMs (plain fp16) ----------------
template<int EPI>
__global__ __launch_bounds__(256) void t_moe_gu(const float* __restrict__ Wall)
{
  const int e = g_tileexp[blockIdx.y];
  if (e < 0) return;
  SMEM_F16S1;
  float acc[4][4][4] = {};
  const int m0 = blockIdx.y * 128, n0 = blockIdx.x * 128;
  const float* B = Wall + (size_t)e * FF * DM;
  f16_tile16<true,1>(acc, g_xln, DM, g_rows, m0, B, DM, n0, 0, DM, Ah, nullptr, Bh, nullptr);
  EPI_SETUP();
#pragma unroll
  for (int i = 0; i < 4; i++)
#pragma unroll
    for (int j = 0; j < 4; j++) {
      const int row = m0 + wm*64 + i*16 + g;
      const int col = n0 + wn*32 + j*8 + tg*2;
      float* p0 = g_gbuf + (size_t)row*FF + col;
      float* p1 = g_gbuf + (size_t)(row+8)*FF + col;
      if (EPI == 0) {
        *(float2*)p0 = make_float2(acc[i][j][0], acc[i][j][1]);
        *(float2*)p1 = make_float2(acc[i][j][2], acc[i][j][3]);
      } else {
        float2 g0 = *(float2*)p0;
        float2 g1 = *(float2*)p1;
        float2 v0, v1;
        v0.x = (g0.x/(1.f+expf(-g0.x))) * acc[i][j][0];
        v0.y = (g0.y/(1.f+expf(-g0.y))) * acc[i][j][1];
        v1.x = (g1.x/(1.f+expf(-g1.x))) * acc[i][j][2];
        v1.y = (g1.y/(1.f+expf(-g1.y))) * acc[i][j][3];
        *(float2*)p0 = v0;
        *(float2*)p1 = v1;
      }
    }
}

__global__ __launch_bounds__(256) void t_moe_down(const float* __restrict__ Wall)
{
  const int e = g_tileexp[blockIdx.y];
  if (e < 0) return;
  SMEM_F16S1;
  float acc[4][4][4] = {};
  const int m0 = blockIdx.y * 128, n0 = blockIdx.x * 128;
  const float* B = Wall + (size_t)e * DM * FF;
  f16_tile16<true,1>(acc, g_gbuf, FF, nullptr, m0, B, FF, n0, 0, FF, Ah, nullptr, Bh, nullptr);
  EPI_SETUP();
#pragma unroll
  for (int i = 0; i < 4; i++)
#pragma unroll
    for (int j = 0; j < 4; j++) {
      const int row = m0 + wm*64 + i*16 + g;
      const int col = n0 + wn*32 + j*8 + tg*2;
      const float w0 = g_wv[row], w1 = g_wv[row+8];
      *(float2*)(g_dout + (size_t)row*DM + col)     = make_float2(acc[i][j][0]*w0, acc[i][j][1]*w0);
      *(float2*)(g_dout + (size_t)(row+8)*DM + col) = make_float2(acc[i][j][2]*w1, acc[i][j][3]*w1);
    }
}

__global__ __launch_bounds__(256) void k_combine(float* __restrict__ out)
{
  const int t = blockIdx.y;
  const int d = blockIdx.x * 256 + threadIdx.x;
  const int s0 = g_slot[t*2], s1 = g_slot[t*2+1];
  out[(size_t)t*DM + d] = g_dout[(size_t)s0*DM + d] + g_dout[(size_t)s1*DM + d];
}

// ---------------- launch ----------------
extern "C" void kernel_launch(void* const* d_in, const int* in_sizes, int n_in,
                              void* d_out, int out_size)
{
  const float* hidden = (const float*)d_in[0];
  const float* cosb   = (const float*)d_in[1];
  const float* sinb   = (const float*)d_in[2];
  const float* ln1w   = (const float*)d_in[3];
  const float* ln1b   = (const float*)d_in[4];
  const float* ln2w   = (const float*)d_in[5];
  const float* ln2b   = (const float*)d_in[6];
  const float* wqkv   = (const float*)d_in[7];
  const float* bqkv   = (const float*)d_in[8];
  const float* wo     = (const float*)d_in[9];
  const float* bo     = (const float*)d_in[10];
  const float* gatew  = (const float*)d_in[11];
  const float* wgate  = (const float*)d_in[12];
  const float* wup    = (const float*)d_in[13];
  const float* wdown  = (const float*)d_in[14];
  float* out = (float*)d_out;

  k_zero<<<1, 32>>>();
  k_ln1<<<SS, 256>>>(hidden, ln1w, ln1b);
  t_gemm_qkv<<<dim3(QKVN/128, SS/128), 256>>>(wqkv, bqkv);
  k_rope<<<dim3(QKVN/256, SS), 256>>>(cosb, sinb);
  t_scores<<<dim3(SS/128, SS/128, NH), 256>>>(0.08838834764831845f);
  k_softmax<<<dim3(SS, NH), 256>>>();
  t_pv<<<dim3(1, SS/128, NH), 256>>>();
  t_oproj<<<dim3(DM/128, SS/128), 256>>>(wo, bo, hidden);
  if (out_size >= 2 * SS * DM)
    k_copyres<<<(SS*DM/4)/256, 256>>>(out + (size_t)SS*DM);
  k_ln2<<<SS, 256>>>(ln2w, ln2b);
  k_router<<<SS, 256>>>(gatew);
  k_setup<<<1, 256>>>();
  k_scatter<<<(SS + 255)/256, 256>>>();
  t_moe_gu<0><<<dim3(FF/128, MAXTILES), 256>>>(wgate);
  t_moe_gu<1><<<dim3(FF/128, MAXTILES), 256>>>(wup);
  t_moe_down<<<dim3(DM/128, MAXTILES), 256>>>(wdown);
  k_combine<<<dim3(DM/256, SS), 256>>>(out);
}

// round 15
// speedup vs baseline: 3.6207x; 1.0114x over previous
#include <cuda_runtime.h>
#include <cuda_fp16.h>
#include <stdint.h>
#include <stddef.h>
#include <math.h>

#define SS   2048
#define DM   2048
#define NH   16
#define NKV  4
#define HD   128
#define NE   8
#define FF   4096
#define QKVN 3072
#define MAXROWS 5120
#define MAXTILES 40

// ---------------- scratch ----------------
__device__ float g_xln[SS*DM];
__device__ float g_qkv[SS*QKVN];
__device__ float g_Q[NH*SS*HD];
__device__ float g_K[NKV*SS*HD];
__device__ float g_V[NKV*SS*HD];
__device__ float g_P[67108864];
__device__ float g_oc[SS*DM];
__device__ float g_res2[SS*DM];
__device__ float g_dout[MAXROWS*DM];
__device__ float g_topw[SS*2];
__device__ int   g_topid[SS*2];
__device__ int   g_cnt[NE];
__device__ int   g_cnt2[NE];
__device__ int   g_off[NE];
__device__ int   g_rows[MAXROWS];
__device__ float g_wv[MAXROWS];
__device__ int   g_slot[SS*2];
__device__ int   g_tileexp[MAXTILES];

// fp16 scratch
__device__ __half g_xh[SS*DM];
__device__ __half g_gh[MAXROWS*FF];
__device__ __half g_wgh[NE*FF*DM];
__device__ __half g_wuh[NE*FF*DM];
__device__ __half g_wdh[NE*DM*FF];

// ================= fp16 helpers =================
__device__ __forceinline__ void cvt2(float x, float y, unsigned &h, unsigned &l) {
  __half hx = __float2half_rn(x), hy = __float2half_rn(y);
  __half lx = __float2half_rn(x - __half2float(hx));
  __half ly = __float2half_rn(y - __half2float(hy));
  h = (unsigned)__half_as_ushort(hx) | ((unsigned)__half_as_ushort(hy) << 16);
  l = (unsigned)__half_as_ushort(lx) | ((unsigned)__half_as_ushort(ly) << 16);
}
__device__ __forceinline__ unsigned cvt2h(float x, float y) {
  __half hx = __float2half_rn(x), hy = __float2half_rn(y);
  return (unsigned)__half_as_ushort(hx) | ((unsigned)__half_as_ushort(hy) << 16);
}

#define MMA_F16(ACC, A0,A1,A2,A3, B0,B1) \
  asm volatile("mma.sync.aligned.m16n8k16.row.col.f32.f16.f16.f32 " \
    "{%0,%1,%2,%3}, {%4,%5,%6,%7}, {%8,%9}, {%0,%1,%2,%3};" \
    : "+f"((ACC)[0]),"+f"((ACC)[1]),"+f"((ACC)[2]),"+f"((ACC)[3]) \
    : "r"(A0),"r"(A1),"r"(A2),"r"(A3),"r"(B0),"r"(B1))

// ================= mma.sync fp16-split tile (attention chain), BK=16 =================
template<bool BT>
__device__ __forceinline__ void f16_tile16(
    float (&acc)[4][4][4],
    const float* __restrict__ A, int lda, int m0,
    const float* __restrict__ B, int ldb, int n0,
    int kbeg, int kend,
    unsigned* __restrict__ Ah, unsigned* __restrict__ Al,
    unsigned* __restrict__ Bh, unsigned* __restrict__ Bl)
{
  const int tid = threadIdx.x, lane = tid & 31, warp = tid >> 5;
  const int wm = warp & 1, wn = warp >> 1;

  const float* aptr[2]; int aidx[2];
#pragma unroll
  for (int it = 0; it < 2; it++) {
    int q = tid + it*256;
    int m = q >> 2, kq = (q & 3) << 2;
    aptr[it] = A + (size_t)(m0 + m) * lda + kq;
    aidx[it] = (m>>4)*128 + (((kq&8)>>2) | ((m&8)>>3))*32 + (m&7)*4 + ((kq&4)>>1);
  }
  const float* bptr[2]; int bidx[2]; int bkq[2];
#pragma unroll
  for (int it = 0; it < 2; it++) {
    int q = tid + it*256;
    int n, kq;
    if (BT) { n = q >> 2;  kq = (q & 3) << 2; }
    else    { n = q & 127; kq = (q >> 7) << 2; }
    bkq[it] = kq;
    bptr[it] = BT ? (B + (size_t)(n0 + n) * ldb + kq) : (B + n0 + n);
    bidx[it] = (n>>3)*64 + ((kq&8)>>3)*32 + (n&7)*4 + ((kq&4)>>1);
  }

  float4 av[2], bv[2];
  auto load = [&](int k0) {
#pragma unroll
    for (int it = 0; it < 2; it++) {
      av[it] = *(const float4*)(aptr[it] + k0);
      if (BT) {
        bv[it] = *(const float4*)(bptr[it] + k0);
      } else {
        const float* p = bptr[it] + (size_t)(k0 + bkq[it]) * ldb;
        bv[it].x = p[0]; bv[it].y = p[ldb]; bv[it].z = p[2*ldb]; bv[it].w = p[3*ldb];
      }
    }
  };
  auto store = [&](int buf) {
#pragma unroll
    for (int it = 0; it < 2; it++) {
      unsigned h0,l0,h1,l1;
      cvt2(av[it].x, av[it].y, h0, l0);
      cvt2(av[it].z, av[it].w, h1, l1);
      *(uint2*)(Ah + buf*1024 + aidx[it]) = make_uint2(h0, h1);
      *(uint2*)(Al + buf*1024 + aidx[it]) = make_uint2(l0, l1);
      cvt2(bv[it].x, bv[it].y, h0, l0);
      cvt2(bv[it].z, bv[it].w, h1, l1);
      *(uint2*)(Bh + buf*1024 + bidx[it]) = make_uint2(h0, h1);
      *(uint2*)(Bl + buf*1024 + bidx[it]) = make_uint2(l0, l1);
    }
  };
  auto comp = [&](int buf) {
    unsigned ah[4][4], al[4][4], bh[4][2], bl[4][2];
#pragma unroll
    for (int i = 0; i < 4; i++)
#pragma unroll
      for (int e = 0; e < 4; e++) {
        int off = buf*1024 + (wm*4 + i)*128 + e*32 + lane;
        ah[i][e] = Ah[off];
        al[i][e] = Al[off];
      }
#pragma unroll
    for (int j = 0; j < 4; j++)
#pragma unroll
      for (int e = 0; e < 2; e++) {
        int off = buf*1024 + (wn*4 + j)*64 + e*32 + lane;
        bh[j][e] = Bh[off];
        bl[j][e] = Bl[off];
      }
#pragma unroll
    for (int i = 0; i < 4; i++)
#pragma unroll
      for (int j = 0; j < 4; j++) {
        MMA_F16(acc[i][j], al[i][0],al[i][1],al[i][2],al[i][3], bh[j][0],bh[j][1]);
        MMA_F16(acc[i][j], ah[i][0],ah[i][1],ah[i][2],ah[i][3], bl[j][0],bl[j][1]);
        MMA_F16(acc[i][j], ah[i][0],ah[i][1],ah[i][2],ah[i][3], bh[j][0],bh[j][1]);
      }
  };

  load(kbeg);
  store(0);
  __syncthreads();
  int buf = 0;
  for (int k0 = kbeg + 16; k0 < kend; k0 += 16) {
    load(k0);
    comp(buf);
    store(buf ^ 1);
    __syncthreads();
    buf ^= 1;
  }
  comp(buf);
}

#define SMEM_F16S3 \
  __shared__ __align__(16) unsigned Ah[2*1024]; \
  __shared__ __align__(16) unsigned Al[2*1024]; \
  __shared__ __align__(16) unsigned Bh[2*1024]; \
  __shared__ __align__(16) unsigned Bl[2*1024];

#define EPI_SETUP() \
  const int lane = threadIdx.x & 31, warp = threadIdx.x >> 5; \
  const int wm = warp & 1, wn = warp >> 1; \
  const int g = lane >> 2, tg = lane & 3;

// ---------------- LayerNorm ----------------
template<bool ALSO_H>
__device__ __forceinline__ void ln_body(const float* __restrict__ x,
    const float* __restrict__ w, const float* __restrict__ b,
    float* __restrict__ y, __half* __restrict__ yh)
{
  float s = 0.f, ss = 0.f;
  for (int d = threadIdx.x*4; d < DM; d += 1024) {
    float4 v = *(const float4*)(x + d);
    s  += v.x + v.y + v.z + v.w;
    ss += v.x*v.x + v.y*v.y + v.z*v.z + v.w*v.w;
  }
  __shared__ float shA[8], shB[8];
  const int lane = threadIdx.x & 31, wi = threadIdx.x >> 5;
  for (int o = 16; o; o >>= 1) { s += __shfl_xor_sync(0xffffffffu, s, o); ss += __shfl_xor_sync(0xffffffffu, ss, o); }
  if (lane == 0) { shA[wi] = s; shB[wi] = ss; }
  __syncthreads();
  float st = 0.f, sst = 0.f;
#pragma unroll
  for (int k = 0; k < 8; k++) { st += shA[k]; sst += shB[k]; }
  const float mean = st / (float)DM;
  const float var  = sst / (float)DM - mean*mean;
  const float rstd = rsqrtf(var + 1e-5f);
  for (int d = threadIdx.x*4; d < DM; d += 1024) {
    float4 v = *(const float4*)(x + d);
    float4 wv = *(const float4*)(w + d);
    float4 bv = *(const float4*)(b + d);
    float4 o;
    o.x = (v.x-mean)*rstd*wv.x + bv.x;
    o.y = (v.y-mean)*rstd*wv.y + bv.y;
    o.z = (v.z-mean)*rstd*wv.z + bv.z;
    o.w = (v.w-mean)*rstd*wv.w + bv.w;
    *(float4*)(y + d) = o;
    if (ALSO_H)
      *(uint2*)(yh + d) = make_uint2(cvt2h(o.x, o.y), cvt2h(o.z, o.w));
  }
}

__global__ __launch_bounds__(256) void k_ln1(const float* __restrict__ hidden,
    const float* __restrict__ w, const float* __restrict__ b)
{
  const int row = blockIdx.x;
  ln_body<false>(hidden + (size_t)row*DM, w, b, g_xln + (size_t)row*DM, nullptr);
}

__global__ __launch_bounds__(256) void k_ln2(const float* __restrict__ w, const float* __restrict__ b)
{
  const int row = blockIdx.x;
  ln_body<true>(g_res2 + (size_t)row*DM, w, b, g_xln + (size_t)row*DM,
                g_xh + (size_t)row*DM);
}

// convert all expert weights to fp16
__global__ __launch_bounds__(256) void k_cvtw(const float* __restrict__ wg,
    const float* __restrict__ wu, const float* __restrict__ wd)
{
  const size_t N = (size_t)NE*FF*DM;
  for (size_t i = ((size_t)blockIdx.x*256 + threadIdx.x)*4; i < N;
       i += (size_t)gridDim.x*1024) {
    float4 a = *(const float4*)(wg+i);
    *(uint2*)(g_wgh+i) = make_uint2(cvt2h(a.x,a.y), cvt2h(a.z,a.w));
    float4 b = *(const float4*)(wu+i);
    *(uint2*)(g_wuh+i) = make_uint2(cvt2h(b.x,b.y), cvt2h(b.z,b.w));
    float4 c = *(const float4*)(wd+i);
    *(uint2*)(g_wdh+i) = make_uint2(cvt2h(c.x,c.y), cvt2h(c.z,c.w));
  }
}

// ---------------- QKV GEMM (fp16-split) ----------------
__global__ __launch_bounds__(256) void t_gemm_qkv(const float* __restrict__ W,
                                                  const float* __restrict__ bias)
{
  SMEM_F16S3;
  float acc[4][4][4] = {};
  const int m0 = blockIdx.y * 128, n0 = blockIdx.x * 128;
  f16_tile16<false>(acc, g_xln, DM, m0, W, QKVN, n0, 0, DM, Ah, Al, Bh, Bl);
  EPI_SETUP();
#pragma unroll
  for (int i = 0; i < 4; i++)
#pragma unroll
    for (int j = 0; j < 4; j++) {
      const int row = m0 + wm*64 + i*16 + g;
      const int col = n0 + wn*32 + j*8 + tg*2;
      const float b0 = bias[col], b1 = bias[col+1];
      *(float2*)(g_qkv + (size_t)row*QKVN + col)     = make_float2(acc[i][j][0]+b0, acc[i][j][1]+b1);
      *(float2*)(g_qkv + (size_t)(row+8)*QKVN + col) = make_float2(acc[i][j][2]+b0, acc[i][j][3]+b1);
    }
}

// ---------------- RoPE + split ----------------
__global__ __launch_bounds__(256) void k_rope(const float* __restrict__ cosb,
                                              const float* __restrict__ sinb)
{
  const int s = blockIdx.y;
  const int col = blockIdx.x * 256 + threadIdx.x;
  const float* qrow = g_qkv + (size_t)s * QKVN;
  const float x = qrow[col];
  if (col < NH*HD) {
    const int h = col >> 7, d = col & 127;
    const float c = cosb[s*HD+d], sn = sinb[s*HD+d];
    const float p = (d < 64) ? -qrow[col+64] : qrow[col-64];
    g_Q[((size_t)h*SS + s)*HD + d] = x*c + p*sn;
  } else if (col < (NH+NKV)*HD) {
    const int cc = col - NH*HD;
    const int h = cc >> 7, d = cc & 127;
    const float c = cosb[s*HD+d], sn = sinb[s*HD+d];
    const float p = (d < 64) ? -qrow[col+64] : qrow[col-64];
    g_K[((size_t)h*SS + s)*HD + d] = x*c + p*sn;
  } else {
    const int cc = col - (NH+NKV)*HD;
    const int h = cc >> 7, d = cc & 127;
    g_V[((size_t)h*SS + s)*HD + d] = x;
  }
}

// ---------------- scores (fp16-split) ----------------
__global__ __launch_bounds__(256) void t_scores(float scale)
{
  if (blockIdx.x > blockIdx.y) return;
  const int h = blockIdx.z;
  SMEM_F16S3;
  float acc[4][4][4] = {};
  const int m0 = blockIdx.y * 128, n0 = blockIdx.x * 128;
  f16_tile16<true>(acc, g_Q + (size_t)h*SS*HD, HD, m0,
                   g_K + (size_t)(h>>2)*SS*HD, HD, n0, 0, HD, Ah, Al, Bh, Bl);
  EPI_SETUP();
  float* Ph = g_P + (size_t)h*SS*SS;
#pragma unroll
  for (int i = 0; i < 4; i++)
#pragma unroll
    for (int j = 0; j < 4; j++) {
      const int row = m0 + wm*64 + i*16 + g;
      const int col = n0 + wn*32 + j*8 + tg*2;
      *(float2*)(Ph + (size_t)row*SS + col)     = make_float2(acc[i][j][0]*scale, acc[i][j][1]*scale);
      *(float2*)(Ph + (size_t)(row+8)*SS + col) = make_float2(acc[i][j][2]*scale, acc[i][j][3]*scale);
    }
}

// ---------------- softmax ----------------
__global__ __launch_bounds__(256) void k_softmax()
{
  const int i = blockIdx.x, h = blockIdx.y;
  float* row = g_P + ((size_t)h*SS + i)*SS;
  const int jm = i;
  const int jend = ((i >> 7) + 1) << 7;
  __shared__ float buf[2048];
  __shared__ float redA[8], redB[8];
  const int tid = threadIdx.x;
  float mx = -1e30f;
  for (int j = tid; j <= jm; j += 256) { float v = row[j]; buf[j] = v; mx = fmaxf(mx, v); }
  for (int o = 16; o; o >>= 1) mx = fmaxf(mx, __shfl_xor_sync(0xffffffffu, mx, o));
  if ((tid & 31) == 0) redA[tid >> 5] = mx;
  __syncthreads();
  float m = redA[0];
#pragma unroll
  for (int k = 1; k < 8; k++) m = fmaxf(m, redA[k]);
  float s = 0.f;
  for (int j = tid; j <= jm; j += 256) { float e = expf(buf[j] - m); buf[j] = e; s += e; }
  for (int o = 16; o; o >>= 1) s += __shfl_xor_sync(0xffffffffu, s, o);
  if ((tid & 31) == 0) redB[tid >> 5] = s;
  __syncthreads();
  float st = 0.f;
#pragma unroll
  for (int k = 0; k < 8; k++) st += redB[k];
  const float inv = 1.f / st;
  for (int j = tid; j < jend; j += 256) row[j] = (j <= jm) ? buf[j]*inv : 0.f;
}

// ---------------- PV (fp16-split) ----------------
__global__ __launch_bounds__(256) void t_pv()
{
  const int h = blockIdx.z, bm = blockIdx.y;
  SMEM_F16S3;
  float acc[4][4][4] = {};
  const int m0 = bm * 128;
  const int kend = (bm + 1) * 128;
  f16_tile16<false>(acc, g_P + (size_t)h*SS*SS, SS, m0,
                    g_V + (size_t)(h>>2)*SS*HD, HD, 0, 0, kend, Ah, Al, Bh, Bl);
  EPI_SETUP();
#pragma unroll
  for (int i = 0; i < 4; i++)
#pragma unroll
    for (int j = 0; j < 4; j++) {
      const int row = m0 + wm*64 + i*16 + g;
      const int col = wn*32 + j*8 + tg*2;
      *(float2*)(g_oc + (size_t)row*DM + h*HD + col)     = make_float2(acc[i][j][0], acc[i][j][1]);
      *(float2*)(g_oc + (size_t)(row+8)*DM + h*HD + col) = make_float2(acc[i][j][2], acc[i][j][3]);
    }
}

// ---------------- O proj + residual (fp16-split) ----------------
__global__ __launch_bounds__(256) void t_oproj(const float* __restrict__ W,
    const float* __restrict__ bias, const float* __restrict__ resid)
{
  SMEM_F16S3;
  float acc[4][4][4] = {};
  const int m0 = blockIdx.y * 128, n0 = blockIdx.x * 128;
  f16_tile16<false>(acc, g_oc, DM, m0, W, DM, n0, 0, DM, Ah, Al, Bh, Bl);
  EPI_SETUP();
#pragma unroll
  for (int i = 0; i < 4; i++)
#pragma unroll
    for (int j = 0; j < 4; j++) {
      const int row = m0 + wm*64 + i*16 + g;
      const int col = n0 + wn*32 + j*8 + tg*2;
      const float b0 = bias[col], b1 = bias[col+1];
      float2 r0 = *(const float2*)(resid + (size_t)row*DM + col);
      float2 r1 = *(const float2*)(resid + (size_t)(row+8)*DM + col);
      *(float2*)(g_res2 + (size_t)row*DM + col)     = make_float2(acc[i][j][0]+b0+r0.x, acc[i][j][1]+b1+r0.y);
      *(float2*)(g_res2 + (size_t)(row+8)*DM + col) = make_float2(acc[i][j][2]+b0+r1.x, acc[i][j][3]+b1+r1.y);
    }
}

__global__ __launch_bounds__(256) void k_copyres(float* __restrict__ dst)
{
  const int i = blockIdx.x * 256 + threadIdx.x;
  ((float4*)dst)[i] = ((const float4*)g_res2)[i];
}

// ---------------- router + sparsemixer ----------------
__global__ void k_zero() { if (threadIdx.x < NE) g_cnt[threadIdx.x] = 0; }

__global__ __launch_bounds__(256) void k_router(const float* __restrict__ gw)
{
  const int t = blockIdx.x;
  const float* x = g_xln + (size_t)t * DM;
  float acc[NE];
#pragma unroll
  for (int e = 0; e < NE; e++) acc[e] = 0.f;
  for (int d = threadIdx.x; d < DM; d += 256) {
    const float xv = x[d];
    const float* gr = gw + d * NE;
#pragma unroll
    for (int e = 0; e < NE; e++) acc[e] += xv * gr[e];
  }
  __shared__ float sh[NE][8];
  const int lane = threadIdx.x & 31, w = threadIdx.x >> 5;
#pragma unroll
  for (int e = 0; e < NE; e++) {
    float v = acc[e];
    for (int o = 16; o; o >>= 1) v += __shfl_xor_sync(0xffffffffu, v, o);
    if (lane == 0) sh[e][w] = v;
  }
  __syncthreads();
  if (threadIdx.x == 0) {
    float s[NE];
#pragma unroll
    for (int e = 0; e < NE; e++) {
      float v = 0.f;
#pragma unroll
      for (int k = 0; k < 8; k++) v += sh[e][k];
      s[e] = v;
    }
    const float teps = 0.02f;
    int i1 = 0;
    for (int e = 1; e < NE; e++) if (s[e] > s[i1]) i1 = e;
    const float mx1 = s[i1];
    float den = 0.f;
    for (int e = 0; e < NE; e++) {
      const float f = fmaxf(fabsf(s[e]), mx1);
      if (!((mx1 - s[e]) / f > teps)) den += expf(s[e] - mx1);
    }
    const float w1 = 1.f / den;
    int i2 = -1; float mx2 = -INFINITY;
    for (int e = 0; e < NE; e++) if (e != i1 && s[e] > mx2) { mx2 = s[e]; i2 = e; }
    float den2 = 0.f;
    for (int e = 0; e < NE; e++) {
      if (e == i1) continue;
      const float f = fmaxf(fabsf(s[e]), mx2);
      if (!((mx2 - s[e]) / f > teps)) den2 += expf(s[e] - mx2);
    }
    const float w2 = 1.f / den2;
    g_topw[t*2] = w1; g_topw[t*2+1] = w2;
    g_topid[t*2] = i1; g_topid[t*2+1] = i2;
    atomicAdd(&g_cnt[i1], 1); atomicAdd(&g_cnt[i2], 1);
  }
}

__global__ __launch_bounds__(256) void k_setup()
{
  const int tid = threadIdx.x;
  if (tid == 0) {
    for (int t = 0; t < MAXTILES; t++) g_tileexp[t] = -1;
    int o = 0;
    for (int e = 0; e < NE; e++) {
      g_off[e] = o;
      const int tiles = (g_cnt[e] + 127) >> 7;
      for (int t = 0; t < tiles; t++) g_tileexp[(o >> 7) + t] = e;
      o += tiles << 7;
    }
  }
  for (int i = tid; i < MAXROWS; i += 256) { g_rows[i] = 0; g_wv[i] = 0.f; }
  if (tid < NE) g_cnt2[tid] = 0;
}

__global__ __launch_bounds__(256) void k_scatter()
{
  const int t = blockIdx.x * 256 + threadIdx.x;
  if (t >= SS) return;
#pragma unroll
  for (int j = 0; j < 2; j++) {
    const int e = g_topid[t*2+j];
    const int pos = g_off[e] + atomicAdd(&g_cnt2[e], 1);
    g_rows[pos] = t;
    g_wv[pos] = g_topw[t*2+j];
    g_slot[t*2+j] = pos;
  }
}

// ================= MoE fp16 direct-load tiles, BK=16 =================
// Fused gate+up: CTA tile 128x128, shared A tile, two B tiles, two accumulators,
// silu(g)*u epilogue -> fp16 g_gh. Per thread per slab: 3 LDG.128 + 3 STS.128, no cvt.
__global__ __launch_bounds__(256) void h_moe_gu()
{
  const int e = g_tileexp[blockIdx.y];
  if (e < 0) return;
  __shared__ __align__(16) unsigned Ah[2*1024];
  __shared__ __align__(16) unsigned Bg[2*1024];
  __shared__ __align__(16) unsigned Bu[2*1024];
  float ag[4][4][4] = {}, au[4][4][4] = {};
  const int m0 = blockIdx.y * 128, n0 = blockIdx.x * 128;
  const int tid = threadIdx.x, lane = tid & 31, warp = tid >> 5;
  const int wm = warp & 1, wn = warp >> 1;

  const int m = tid >> 1, kq = (tid & 1) * 8;
  const int tok = g_rows[m0 + m];
  const __half* ap = g_xh + (size_t)tok*DM + kq;
  const size_t br = (size_t)e*FF + n0 + m;
  const __half* gp = g_wgh + br*DM + kq;
  const __half* up = g_wuh + br*DM + kq;
  const int asto = (m>>4)*128 + (((kq&8)>>2) | ((m&8)>>3))*32 + (m&7)*4;
  const int bsto = (m>>3)*64 + ((kq&8)>>3)*32 + (m&7)*4;

  uint4 av, gv, uv;
  auto load = [&](int k0) {
    av = *(const uint4*)(ap + k0);
    gv = *(const uint4*)(gp + k0);
    uv = *(const uint4*)(up + k0);
  };
  auto store = [&](int buf) {
    *(uint4*)(Ah + buf*1024 + asto) = av;
    *(uint4*)(Bg + buf*1024 + bsto) = gv;
    *(uint4*)(Bu + buf*1024 + bsto) = uv;
  };
  auto comp = [&](int buf) {
    unsigned ah[4][4], bg[4][2], bu[4][2];
#pragma unroll
    for (int i = 0; i < 4; i++)
#pragma unroll
      for (int ee = 0; ee < 4; ee++)
        ah[i][ee] = Ah[buf*1024 + (wm*4 + i)*128 + ee*32 + lane];
#pragma unroll
    for (int j = 0; j < 4; j++)
#pragma unroll
      for (int ee = 0; ee < 2; ee++) {
        int off = buf*1024 + (wn*4 + j)*64 + ee*32 + lane;
        bg[j][ee] = Bg[off];
        bu[j][ee] = Bu[off];
      }
#pragma unroll
    for (int i = 0; i < 4; i++)
#pragma unroll
      for (int j = 0; j < 4; j++) {
        MMA_F16(ag[i][j], ah[i][0],ah[i][1],ah[i][2],ah[i][3], bg[j][0],bg[j][1]);
        MMA_F16(au[i][j], ah[i][0],ah[i][1],ah[i][2],ah[i][3], bu[j][0],bu[j][1]);
      }
  };

  load(0);
  store(0);
  __syncthreads();
  int buf = 0;
  for (int k0 = 16; k0 < DM; k0 += 16) {
    load(k0);
    comp(buf);
    store(buf ^ 1);
    __syncthreads();
    buf ^= 1;
  }
  comp(buf);

  const int g = lane >> 2, tg = lane & 3;
#pragma unroll
  for (int i = 0; i < 4; i++)
#pragma unroll
    for (int j = 0; j < 4; j++) {
      const int row = m0 + wm*64 + i*16 + g;
      const int col = n0 + wn*32 + j*8 + tg*2;
      const float g0 = ag[i][j][0], g1 = ag[i][j][1];
      const float g2 = ag[i][j][2], g3 = ag[i][j][3];
      const float h0 = g0/(1.f+expf(-g0)) * au[i][j][0];
      const float h1 = g1/(1.f+expf(-g1)) * au[i][j][1];
      const float h2 = g2/(1.f+expf(-g2)) * au[i][j][2];
      const float h3 = g3/(1.f+expf(-g3)) * au[i][j][3];
      *(unsigned*)(g_gh + (size_t)row*FF + col)     = cvt2h(h0, h1);
      *(unsigned*)(g_gh + (size_t)(row+8)*FF + col) = cvt2h(h2, h3);
    }
}

// Down: CTA tile 128x128, A = g_gh fp16, B = g_wdh fp16 [DM, FF].
__global__ __launch_bounds__(256) void h_moe_down()
{
  const int e = g_tileexp[blockIdx.y];
  if (e < 0) return;
  __shared__ __align__(16) unsigned Ah[2*1024];
  __shared__ __align__(16) unsigned Bh[2*1024];
  float acc[4][4][4] = {};
  const int m0 = blockIdx.y * 128, n0 = blockIdx.x * 128;
  const int tid = threadIdx.x, lane = tid & 31, warp = tid >> 5;
  const int wm = warp & 1, wn = warp >> 1;

  const int m = tid >> 1, kq = (tid & 1) * 8;
  const __half* ap = g_gh + (size_t)(m0 + m)*FF + kq;
  const __half* bp = g_wdh + ((size_t)e*DM + n0 + m)*FF + kq;
  const int asto = (m>>4)*128 + (((kq&8)>>2) | ((m&8)>>3))*32 + (m&7)*4;
  const int bsto = (m>>3)*64 + ((kq&8)>>3)*32 + (m&7)*4;

  uint4 av, bv;
  auto load = [&](int k0) {
    av = *(const uint4*)(ap + k0);
    bv = *(const uint4*)(bp + k0);
  };
  auto store = [&](int buf) {
    *(uint4*)(Ah + buf*1024 + asto) = av;
    *(uint4*)(Bh + buf*1024 + bsto) = bv;
  };
  auto comp = [&](int buf) {
    unsigned ah[4][4], bh[4][2];
#pragma unroll
    for (int i = 0; i < 4; i++)
#pragma unroll
      for (int ee = 0; ee < 4; ee++)
        ah[i][ee] = Ah[buf*1024 + (wm*4 + i)*128 + ee*32 + lane];
#pragma unroll
    for (int j = 0; j < 4; j++)
#pragma unroll
      for (int ee = 0; ee < 2; ee++)
        bh[j][ee] = Bh[buf*1024 + (wn*4 + j)*64 + ee*32 + lane];
#pragma unroll
    for (int i = 0; i < 4; i++)
#pragma unroll
      for (int j = 0; j < 4; j++)
        MMA_F16(acc[i][j], ah[i][0],ah[i][1],ah[i][2],ah[i][3], bh[j][0],bh[j][1]);
  };

  load(0);
  store(0);
  __syncthreads();
  int buf = 0;
  for (int k0 = 16; k0 < FF; k0 += 16) {
    load(k0);
    comp(buf);
    store(buf ^ 1);
    __syncthreads();
    buf ^= 1;
  }
  comp(buf);

  const int g = lane >> 2, tg = lane & 3;
#pragma unroll
  for (int i = 0; i < 4; i++)
#pragma unroll
    for (int j = 0; j < 4; j++) {
      const int row = m0 + wm*64 + i*16 + g;
      const int col = n0 + wn*32 + j*8 + tg*2;
      const float w0 = g_wv[row], w1 = g_wv[row+8];
      *(float2*)(g_dout + (size_t)row*DM + col)     = make_float2(acc[i][j][0]*w0, acc[i][j][1]*w0);
      *(float2*)(g_dout + (size_t)(row+8)*DM + col) = make_float2(acc[i][j][2]*w1, acc[i][j][3]*w1);
    }
}

__global__ __launch_bounds__(256) void k_combine(float* __restrict__ out)
{
  const int t = blockIdx.y;
  const int d = blockIdx.x * 256 + threadIdx.x;
  const int s0 = g_slot[t*2], s1 = g_slot[t*2+1];
  out[(size_t)t*DM + d] = g_dout[(size_t)s0*DM + d] + g_dout[(size_t)s1*DM + d];
}

// ---------------- launch ----------------
extern "C" void kernel_launch(void* const* d_in, const int* in_sizes, int n_in,
                              void* d_out, int out_size)
{
  const float* hidden = (const float*)d_in[0];
  const float* cosb   = (const float*)d_in[1];
  const float* sinb   = (const float*)d_in[2];
  const float* ln1w   = (const float*)d_in[3];
  const float* ln1b   = (const float*)d_in[4];
  const float* ln2w   = (const float*)d_in[5];
  const float* ln2b   = (const float*)d_in[6];
  const float* wqkv   = (const float*)d_in[7];
  const float* bqkv   = (const float*)d_in[8];
  const float* wo     = (const float*)d_in[9];
  const float* bo     = (const float*)d_in[10];
  const float* gatew  = (const float*)d_in[11];
  const float* wgate  = (const float*)d_in[12];
  const float* wup    = (const float*)d_in[13];
  const float* wdown  = (const float*)d_in[14];
  float* out = (float*)d_out;

  k_zero<<<1, 32>>>();
  k_cvtw<<<16384, 256>>>(wgate, wup, wdown);
  k_ln1<<<SS, 256>>>(hidden, ln1w, ln1b);
  t_gemm_qkv<<<dim3(QKVN/128, SS/128), 256>>>(wqkv, bqkv);
  k_rope<<<dim3(QKVN/256, SS), 256>>>(cosb, sinb);
  t_scores<<<dim3(SS/128, SS/128, NH), 256>>>(0.08838834764831845f);
  k_softmax<<<dim3(SS, NH), 256>>>();
  t_pv<<<dim3(1, SS/128, NH), 256>>>();
  t_oproj<<<dim3(DM/128, SS/128), 256>>>(wo, bo, hidden);
  if (out_size >= 2 * SS * DM)
    k_copyres<<<(SS*DM/4)/256, 256>>>(out + (size_t)SS*DM);
  k_ln2<<<SS, 256>>>(ln2w, ln2b);
  k_router<<<SS, 256>>>(gatew);
  k_setup<<<1, 256>>>();
  k_scatter<<<(SS + 255)/256, 256>>>();
  h_moe_gu<<<dim3(FF/128, MAXTILES), 256>>>();
  h_moe_down<<<dim3(DM/128, MAXTILES), 256>>>();
  k_combine<<<dim3(DM/256, SS), 256>>>(out);
}